// round 3
// baseline (speedup 1.0000x reference)
#include <cuda_runtime.h>
#include <math.h>

#define T_ 2048
#define C_ 2048
#define H_ 32
#define S_ 64
#define HKV_ 8
#define LMAA_ 32
#define LDEC_ 64

// ---------------- scratch (static device arrays; no runtime alloc) ----------------
__device__ float g_sx [T_*C_];
__device__ float g_xxx[T_*C_];
__device__ float g_t1 [T_*5*LMAA_];
__device__ float g_xr [T_*C_];
__device__ float g_xk [T_*C_];
__device__ float g_xv [T_*C_];
__device__ float g_xw [T_*C_];
__device__ float g_xg [T_*C_];
__device__ float g_r  [T_*C_];
__device__ float g_k  [T_*HKV_*S_];
__device__ float g_v  [T_*HKV_*S_];
__device__ float g_t2 [T_*LDEC_];
__device__ float g_ew [T_*C_];
__device__ float g_keff[T_*C_];
__device__ float g_gate[T_*C_];
__device__ float g_out[T_*C_];
__device__ float g_sfin[H_*S_*S_];

// ---------------- epilogue ids ----------------
#define EPI_NONE  0
#define EPI_TANH  1
#define EPI_SIG   2
#define EPI_MIX   3   // out = aux1[idx] + aux2[idx]*(vec[col] + acc)
#define EPI_DECAY 4   // out = exp(max(-exp(acc + vec[col]), -5))

// ---------------- generic f32 GEMM: C[M,N] = A[M,K] @ B[K,N] ----------------
// BM=BN=128, BK=8, 256 threads, 8x8 per thread. M must be a multiple of 128;
// K a multiple of 8; N arbitrary (guarded).
template<int EPI>
__global__ __launch_bounds__(256)
void sgemm(const float* __restrict__ A, int lda,
           const float* __restrict__ B, int ldb,
           float* __restrict__ Cout, int ldc,
           int N, int K,
           const float* __restrict__ aux1,
           const float* __restrict__ aux2,
           const float* __restrict__ vec)
{
    __shared__ float As[8][128];
    __shared__ float Bs[8][128];

    const int tid = threadIdx.x;
    const int bx = blockIdx.x;   // N tile
    const int by = blockIdx.y;   // M tile

    const int arow = tid >> 1;          // 0..127
    const int acol = (tid & 1) * 4;     // 0 or 4
    const int brow = tid >> 5;          // 0..7
    const int bcol = (tid & 31) * 4;    // 0..124

    const int tx = tid & 15;            // col group
    const int ty = tid >> 4;            // row group

    float acc[8][8];
    #pragma unroll
    for (int i = 0; i < 8; i++)
        #pragma unroll
        for (int j = 0; j < 8; j++) acc[i][j] = 0.f;

    const float* Ap = A + (size_t)(by * 128) * lda;

    for (int k0 = 0; k0 < K; k0 += 8) {
        // stage A (always in-bounds: M multiple of 128, K multiple of 8)
        float4 av = *(const float4*)(Ap + (size_t)arow * lda + k0 + acol);
        As[acol + 0][arow] = av.x;
        As[acol + 1][arow] = av.y;
        As[acol + 2][arow] = av.z;
        As[acol + 3][arow] = av.w;
        // stage B (guard N)
        int gcol = bx * 128 + bcol;
        if (gcol + 3 < N) {
            float4 bv = *(const float4*)(B + (size_t)(k0 + brow) * ldb + gcol);
            *(float4*)&Bs[brow][bcol] = bv;
        } else {
            #pragma unroll
            for (int j = 0; j < 4; j++)
                Bs[brow][bcol + j] = (gcol + j < N) ? B[(size_t)(k0 + brow) * ldb + gcol + j] : 0.f;
        }
        __syncthreads();

        #pragma unroll
        for (int kk = 0; kk < 8; kk++) {
            float af[8], bf[8];
            *(float4*)&af[0] = *(const float4*)&As[kk][ty * 8];
            *(float4*)&af[4] = *(const float4*)&As[kk][ty * 8 + 4];
            *(float4*)&bf[0] = *(const float4*)&Bs[kk][tx * 8];
            *(float4*)&bf[4] = *(const float4*)&Bs[kk][tx * 8 + 4];
            #pragma unroll
            for (int i = 0; i < 8; i++)
                #pragma unroll
                for (int j = 0; j < 8; j++)
                    acc[i][j] = fmaf(af[i], bf[j], acc[i][j]);
        }
        __syncthreads();
    }

    // epilogue + store
    #pragma unroll
    for (int i = 0; i < 8; i++) {
        int row = by * 128 + ty * 8 + i;
        #pragma unroll
        for (int j = 0; j < 8; j++) {
            int col = bx * 128 + tx * 8 + j;
            if (col >= N) continue;
            size_t idx = (size_t)row * ldc + col;
            float a = acc[i][j];
            float val;
            if (EPI == EPI_NONE)       val = a;
            else if (EPI == EPI_TANH)  val = tanhf(a);
            else if (EPI == EPI_SIG)   val = 1.f / (1.f + expf(-a));
            else if (EPI == EPI_MIX)   val = aux1[idx] + aux2[idx] * (vec[col] + a);
            else {  // EPI_DECAY
                float lw = fmaxf(-expf(a + vec[col]), -5.0f);
                val = expf(lw);
            }
            Cout[idx] = val;
        }
    }
}

// ---------------- elementwise kernels ----------------
__global__ void k_shift(const float* __restrict__ x, const float* __restrict__ state,
                        const unsigned char* __restrict__ ns,
                        const float* __restrict__ maa_x)
{
    int idx = blockIdx.x * blockDim.x + threadIdx.x;
    if (idx >= T_ * C_) return;
    int t = idx >> 11;        // / 2048
    int c = idx & 2047;
    float prev = (t == 0) ? state[c] : x[idx - C_];
    if (ns[t]) prev = 0.f;
    float s = prev - x[idx];
    g_sx[idx]  = s;
    g_xxx[idx] = x[idx] + s * maa_x[c];
}

__global__ void k_keff()
{
    int idx = blockIdx.x * blockDim.x + threadIdx.x;
    if (idx >= T_ * C_) return;
    int t = idx >> 11;
    int c = idx & 2047;
    int h = c >> 6;
    int s = c & 63;
    float kv = g_k[t * (HKV_ * S_) + (h >> 2) * S_ + s];
    g_keff[idx] = kv * (1.f - g_ew[idx]);
}

__global__ void k_gate_mul()
{
    int idx = blockIdx.x * blockDim.x + threadIdx.x;
    if (idx >= T_ * C_) return;
    g_out[idx] = g_out[idx] * g_gate[idx];
}

// ---------------- the RWKV scan: one CTA per head ----------------
__global__ __launch_bounds__(512)
void k_scan(const float* __restrict__ state, const unsigned char* __restrict__ ns)
{
    const int h   = blockIdx.x;
    const int tid = threadIdx.x;
    const int vcol = tid & 63;
    const int kg   = tid >> 6;      // 0..7 -> owns k rows kg*8..kg*8+7

    float s[8];
    #pragma unroll
    for (int j = 0; j < 8; j++)
        s[j] = state[C_ + h * (S_ * S_) + (kg * 8 + j) * S_ + vcol];

    __shared__ float sh[4 * 64];    // [r | keff | ew | v]
    __shared__ float pbuf[512];

    for (int t = 0; t < T_; t++) {
        if (tid < 256) {
            int a = tid >> 6, i = tid & 63;
            float val;
            if (a == 0)      val = g_r   [(size_t)t * C_ + h * S_ + i];
            else if (a == 1) val = g_keff[(size_t)t * C_ + h * S_ + i];
            else if (a == 2) val = g_ew  [(size_t)t * C_ + h * S_ + i];
            else             val = g_v   [(size_t)t * (HKV_ * S_) + (h >> 2) * S_ + i];
            sh[a * 64 + i] = val;
        }
        bool reset = (ns[t] != 0);
        __syncthreads();

        float vv = sh[3 * 64 + vcol];
        float ps = 0.f;
        #pragma unroll
        for (int j = 0; j < 8; j++) {
            int kk = kg * 8 + j;
            float sj = reset ? 0.f : s[j];
            sj = fmaf(sj, sh[2 * 64 + kk], sh[64 + kk] * vv);
            s[j] = sj;
            ps = fmaf(sh[kk], sj, ps);
        }
        pbuf[tid] = ps;
        __syncthreads();

        if (tid < 64) {
            float o = 0.f;
            #pragma unroll
            for (int g2 = 0; g2 < 8; g2++) o += pbuf[g2 * 64 + tid];
            g_out[(size_t)t * C_ + h * S_ + tid] = o;
        }
        __syncthreads();
    }

    #pragma unroll
    for (int j = 0; j < 8; j++)
        g_sfin[h * (S_ * S_) + (kg * 8 + j) * S_ + vcol] = s[j];
}

// ---------------- new_state writer ----------------
__global__ void k_state(float* __restrict__ dout, const float* __restrict__ x,
                        const int* __restrict__ lenp)
{
    int idx = blockIdx.x * blockDim.x + threadIdx.x;
    int L = lenp ? lenp[0] : T_;
    if (idx < C_)
        dout[(size_t)T_ * C_ + idx] = x[(size_t)(L - 1) * C_ + idx];
    if (idx < H_ * S_ * S_)
        dout[(size_t)T_ * C_ + C_ + idx] = g_sfin[idx];
}

// ---------------- host-side orchestration ----------------
template <typename Sym>
static float* devaddr(Sym& sym) {
    void* p = nullptr;
    cudaGetSymbolAddress(&p, sym);
    return (float*)p;
}

extern "C" void kernel_launch(void* const* d_in, const int* in_sizes, int n_in,
                              void* d_out, int out_size)
{
    int i = 0;
    const float* x       = (const float*)d_in[i++];
    const float* state   = (const float*)d_in[i++];
    const unsigned char* ns = (const unsigned char*)d_in[i++];
    const int* lenp = nullptr;
    if (n_in >= 20) { lenp = (const int*)d_in[i++]; }
    const float* maa_x = (const float*)d_in[i++];
    const float* maa_r = (const float*)d_in[i++];
    const float* maa_k = (const float*)d_in[i++];
    const float* maa_v = (const float*)d_in[i++];
    const float* maa_w = (const float*)d_in[i++];
    const float* maa_g = (const float*)d_in[i++];
    const float* maa_w1 = (const float*)d_in[i++];  // [C, 160]
    const float* maa_w2 = (const float*)d_in[i++];  // [5, 32, C]
    const float* tdecay = (const float*)d_in[i++];  // [C]
    const float* dec_w1 = (const float*)d_in[i++];  // [C, 64]
    const float* dec_w2 = (const float*)d_in[i++];  // [64, C]
    const float* Wq = (const float*)d_in[i++];      // [C, C]
    const float* Wk = (const float*)d_in[i++];      // [C, 512]
    const float* Wv = (const float*)d_in[i++];      // [C, 512]
    const float* Wg = (const float*)d_in[i++];      // [C, C]
    const float* Wo = (const float*)d_in[i++];      // [C, C]
    float* dout = (float*)d_out;

    float* p_sx   = devaddr(g_sx);
    float* p_xxx  = devaddr(g_xxx);
    float* p_t1   = devaddr(g_t1);
    float* p_xr   = devaddr(g_xr);
    float* p_xk   = devaddr(g_xk);
    float* p_xv   = devaddr(g_xv);
    float* p_xw   = devaddr(g_xw);
    float* p_xg   = devaddr(g_xg);
    float* p_r    = devaddr(g_r);
    float* p_k    = devaddr(g_k);
    float* p_v    = devaddr(g_v);
    float* p_t2   = devaddr(g_t2);
    float* p_ew   = devaddr(g_ew);
    float* p_gate = devaddr(g_gate);
    float* p_out  = devaddr(g_out);

    const int EW = 256;
    const int GE = (T_ * C_ + EW - 1) / EW;

    // 1) token shift + xxx
    k_shift<<<GE, EW>>>(x, state, ns, maa_x);

    dim3 blk(256);
    // 2) t1 = tanh(xxx @ maa_w1)   [T,160]
    {
        dim3 g((160 + 127) / 128, T_ / 128);
        sgemm<EPI_TANH><<<g, blk>>>(p_xxx, C_, maa_w1, 5 * LMAA_, p_t1, 5 * LMAA_,
                                    5 * LMAA_, C_, nullptr, nullptr, nullptr);
    }
    // 3) per-branch mix: xb = x + sx*(maa_b + t1[:,n] @ w2[n])
    {
        dim3 g(C_ / 128, T_ / 128);
        const float* vecs[5] = {maa_r, maa_k, maa_v, maa_w, maa_g};
        float* outs[5] = {p_xr, p_xk, p_xv, p_xw, p_xg};
        for (int n = 0; n < 5; n++)
            sgemm<EPI_MIX><<<g, blk>>>(p_t1 + n * LMAA_, 5 * LMAA_,
                                       maa_w2 + (size_t)n * LMAA_ * C_, C_,
                                       outs[n], C_, C_, LMAA_,
                                       x, p_sx, vecs[n]);
    }
    // 4) r / k / v projections
    {
        dim3 g(C_ / 128, T_ / 128);
        sgemm<EPI_NONE><<<g, blk>>>(p_xr, C_, Wq, C_, p_r, C_, C_, C_, nullptr, nullptr, nullptr);
        dim3 g2((HKV_ * S_) / 128, T_ / 128);
        sgemm<EPI_NONE><<<g2, blk>>>(p_xk, C_, Wk, HKV_ * S_, p_k, HKV_ * S_, HKV_ * S_, C_, nullptr, nullptr, nullptr);
        sgemm<EPI_NONE><<<g2, blk>>>(p_xv, C_, Wv, HKV_ * S_, p_v, HKV_ * S_, HKV_ * S_, C_, nullptr, nullptr, nullptr);
    }
    // 5) decay LoRA: t2 = tanh(xw @ dec_w1); ew = exp(max(-exp(t2@dec_w2 + tdecay), -5))
    {
        dim3 g((LDEC_ + 127) / 128, T_ / 128);
        sgemm<EPI_TANH><<<g, blk>>>(p_xw, C_, dec_w1, LDEC_, p_t2, LDEC_, LDEC_, C_, nullptr, nullptr, nullptr);
        dim3 g2(C_ / 128, T_ / 128);
        sgemm<EPI_DECAY><<<g2, blk>>>(p_t2, LDEC_, dec_w2, C_, p_ew, C_, C_, LDEC_,
                                      nullptr, nullptr, tdecay);
    }
    // 6) keff = repeat(k) * (1 - ew)
    k_keff<<<GE, EW>>>();
    // 7) gate = sigmoid(xg @ Wg)
    {
        dim3 g(C_ / 128, T_ / 128);
        sgemm<EPI_SIG><<<g, blk>>>(p_xg, C_, Wg, C_, p_gate, C_, C_, C_, nullptr, nullptr, nullptr);
    }
    // 8) sequential scan
    k_scan<<<H_, 512>>>(state, ns);
    // 9) y = out * gate
    k_gate_mul<<<GE, EW>>>();
    // 10) final projection: dout = y @ Wo
    {
        dim3 g(C_ / 128, T_ / 128);
        sgemm<EPI_NONE><<<g, blk>>>(p_out, C_, Wo, C_, dout, C_, C_, C_, nullptr, nullptr, nullptr);
    }
    // 11) new_state (only if the harness expects both outputs)
    if (out_size >= T_ * C_ + (S_ + 1) * C_) {
        int n = H_ * S_ * S_;
        k_state<<<(n + EW - 1) / EW, EW>>>(dout, x, lenp);
    }
}

// round 5
// speedup vs baseline: 1.3578x; 1.3578x over previous
#include <cuda_runtime.h>
#include <math.h>

#define T_ 2048
#define C_ 2048
#define H_ 32
#define S_ 64
#define HKV_ 8
#define LMAA_ 32
#define LDEC_ 64
#define SPLITK 8

// ---------------- scratch (static device arrays; no runtime alloc) ----------------
__device__ float g_sx [T_*C_];
__device__ float g_xxx[T_*C_];
__device__ float g_t1 [T_*5*LMAA_];
__device__ float g_xr [T_*C_];
__device__ float g_xk [T_*C_];
__device__ float g_xv [T_*C_];
__device__ float g_xw [T_*C_];
__device__ float g_xg [T_*C_];
__device__ float g_r  [T_*C_];
__device__ float g_k  [T_*HKV_*S_];
__device__ float g_v  [T_*HKV_*S_];
__device__ float g_t2 [T_*LDEC_];
__device__ float g_ew [T_*C_];
__device__ float g_gate[T_*C_];
__device__ float g_out[T_*C_];
__device__ float g_sfin[H_*S_*S_];
__device__ float g_part[SPLITK * T_ * (5*LMAA_)];   // split-K partials (max N=160)

// ---------------- epilogue ids ----------------
#define EPI_NONE  0
#define EPI_SIG   2
#define EPI_MIX   3   // out = aux1[idx] + aux2[idx]*(vec[col] + acc)
#define EPI_DECAY 4   // out = exp(max(-exp(acc + vec[col]), -5))

struct Batch {
    const float* A[8];
    const float* B[8];
    float*       Cc[8];
    const float* vec[8];
};

template<int EPI>
__device__ __forceinline__ float epi_apply(float a, size_t idx, int col,
    const float* __restrict__ aux1, const float* __restrict__ aux2,
    const float* __restrict__ vec)
{
    if (EPI == EPI_SIG)   return 1.f / (1.f + expf(-a));
    if (EPI == EPI_MIX)   return aux1[idx] + aux2[idx] * (vec[col] + a);
    if (EPI == EPI_DECAY) { float lw = fmaxf(-expf(a + vec[col]), -5.0f); return expf(lw); }
    return a;
}

// ---------------- FFMA2 GEMM: C[M,N] = A[M,K] @ B[K,N] ----------------
// BM=BN=128, BK=16, 256 threads, 8x8 per thread as 8x(4 packed f32x2).
// M multiple of 128, K multiple of 16, N arbitrary (guarded).
template<int EPI>
__global__ __launch_bounds__(256, 2)
void gemm128(Batch bt, int lda, int ldb, int ldc, int N, int K,
             const float* __restrict__ aux1, const float* __restrict__ aux2)
{
    __shared__ float2 As[2][16][128];   // duplicated A values (a,a)
    __shared__ float  Bs[2][16][128];

    const int z = blockIdx.z;
    const float* __restrict__ A   = bt.A[z];
    const float* __restrict__ B   = bt.B[z];
    float*       __restrict__ C   = bt.Cc[z];
    const float* __restrict__ vec = bt.vec[z];

    const int tid = threadIdx.x;
    const int bx = blockIdx.x, by = blockIdx.y;
    const int arow = tid >> 1,  acol = (tid & 1) * 8;
    const int brow = tid >> 4,  bcol = (tid & 15) * 8;
    const int tx = tid & 15,    ty = tid >> 4;

    unsigned long long acc[8][4];
    #pragma unroll
    for (int i = 0; i < 8; i++)
        #pragma unroll
        for (int j = 0; j < 4; j++) acc[i][j] = 0ULL;

    const float* Ap = A + (size_t)(by * 128 + arow) * lda + acol;
    const int gcolb = bx * 128 + bcol;

    float4 a0, a1, b0, b1;

    auto loadAB = [&](int k0) {
        a0 = *(const float4*)(Ap + k0);
        a1 = *(const float4*)(Ap + k0 + 4);
        const float* bp = B + (size_t)(k0 + brow) * ldb + gcolb;
        if (gcolb + 7 < N) {
            b0 = *(const float4*)bp;
            b1 = *(const float4*)(bp + 4);
        } else {
            float t[8];
            #pragma unroll
            for (int j = 0; j < 8; j++) t[j] = (gcolb + j < N) ? bp[j] : 0.f;
            b0 = make_float4(t[0], t[1], t[2], t[3]);
            b1 = make_float4(t[4], t[5], t[6], t[7]);
        }
    };
    auto storeAB = [&](int buf) {
        As[buf][acol + 0][arow] = make_float2(a0.x, a0.x);
        As[buf][acol + 1][arow] = make_float2(a0.y, a0.y);
        As[buf][acol + 2][arow] = make_float2(a0.z, a0.z);
        As[buf][acol + 3][arow] = make_float2(a0.w, a0.w);
        As[buf][acol + 4][arow] = make_float2(a1.x, a1.x);
        As[buf][acol + 5][arow] = make_float2(a1.y, a1.y);
        As[buf][acol + 6][arow] = make_float2(a1.z, a1.z);
        As[buf][acol + 7][arow] = make_float2(a1.w, a1.w);
        *(float4*)&Bs[buf][brow][bcol]     = b0;
        *(float4*)&Bs[buf][brow][bcol + 4] = b1;
    };

    loadAB(0);
    storeAB(0);
    __syncthreads();

    const int nt = K >> 4;
    for (int kt = 0; kt < nt; kt++) {
        const int cur = kt & 1;
        if (kt + 1 < nt) loadAB((kt + 1) << 4);

        #pragma unroll
        for (int kk = 0; kk < 16; kk++) {
            unsigned long long a2[8], b2[4];
            const ulonglong2* ap = (const ulonglong2*)&As[cur][kk][ty * 8];
            ulonglong2 w;
            w = ap[0]; a2[0] = w.x; a2[1] = w.y;
            w = ap[1]; a2[2] = w.x; a2[3] = w.y;
            w = ap[2]; a2[4] = w.x; a2[5] = w.y;
            w = ap[3]; a2[6] = w.x; a2[7] = w.y;
            const ulonglong2* bp2 = (const ulonglong2*)&Bs[cur][kk][tx * 8];
            w = bp2[0]; b2[0] = w.x; b2[1] = w.y;
            w = bp2[1]; b2[2] = w.x; b2[3] = w.y;
            #pragma unroll
            for (int i = 0; i < 8; i++)
                #pragma unroll
                for (int j = 0; j < 4; j++)
                    asm("fma.rn.f32x2 %0, %1, %2, %0;"
                        : "+l"(acc[i][j]) : "l"(a2[i]), "l"(b2[j]));
        }

        if (kt + 1 < nt) storeAB(cur ^ 1);
        __syncthreads();
    }

    // epilogue + store
    #pragma unroll
    for (int i = 0; i < 8; i++) {
        const int row = by * 128 + ty * 8 + i;
        float* crow = C + (size_t)row * ldc;
        #pragma unroll
        for (int j = 0; j < 4; j++) {
            const int col = bx * 128 + tx * 8 + 2 * j;
            if (col >= N) continue;
            float lo = __uint_as_float((unsigned)(acc[i][j] & 0xffffffffULL));
            float hi = __uint_as_float((unsigned)(acc[i][j] >> 32));
            size_t idx = (size_t)row * ldc + col;
            lo = epi_apply<EPI>(lo, idx, col, aux1, aux2, vec);
            if (col + 1 < N) {
                hi = epi_apply<EPI>(hi, idx + 1, col + 1, aux1, aux2, vec);
                *(float2*)&crow[col] = make_float2(lo, hi);
            } else {
                crow[col] = lo;
            }
        }
    }
}

// ---------------- split-K reducer + tanh ----------------
__global__ void k_red_tanh(const float* __restrict__ part, float* __restrict__ out,
                           int n, int stride)
{
    int i = blockIdx.x * blockDim.x + threadIdx.x;
    if (i >= n) return;
    float s = 0.f;
    #pragma unroll
    for (int z = 0; z < SPLITK; z++) s += part[(size_t)z * stride + i];
    out[i] = tanhf(s);
}

// ---------------- elementwise: token shift ----------------
__global__ void k_shift(const float* __restrict__ x, const float* __restrict__ state,
                        const unsigned char* __restrict__ ns,
                        const float* __restrict__ maa_x)
{
    int idx = blockIdx.x * blockDim.x + threadIdx.x;
    if (idx >= T_ * C_) return;
    int t = idx >> 11;
    int c = idx & 2047;
    float prev = (t == 0) ? state[c] : x[idx - C_];
    if (ns[t]) prev = 0.f;
    float s = prev - x[idx];
    g_sx[idx]  = s;
    g_xxx[idx] = x[idx] + s * maa_x[c];
}

// ---------------- the RWKV scan: one CTA per head ----------------
// 512 threads: vcol = tid>>3 (0..63), kg = tid&7 (each thread owns 8 k-rows).
// 8-deep register prefetch into ping-pong shared staging; 1 barrier per step.
// f32x2-packed state update; shfl_xor reduction; gate fused into output.
__global__ __launch_bounds__(512)
void k_scan(const float* __restrict__ state, const unsigned char* __restrict__ ns)
{
    const int h = blockIdx.x;
    const int tid = threadIdx.x;
    const int vcol = tid >> 3;
    const int kg = tid & 7;

    // packed state: s2[j2] = (row kg*8+2*j2, row kg*8+2*j2+1) at column vcol
    unsigned long long s2[4];
    #pragma unroll
    for (int j2 = 0; j2 < 4; j2++) {
        float slo = state[C_ + h * 4096 + (kg * 8 + 2 * j2) * 64 + vcol];
        float shi = state[C_ + h * 4096 + (kg * 8 + 2 * j2 + 1) * 64 + vcol];
        asm("mov.b64 %0, {%1, %2};" : "=l"(s2[j2]) : "f"(slo), "f"(shi));
    }

    __shared__ float sh[2][5 * 64];       // [r | keff | ew | v | gate]
    __shared__ unsigned char nsh[T_];
    for (int i = tid; i < T_; i += 512) nsh[i] = ns[i];

    const int a  = tid >> 6;              // loader group (a<5 loads)
    const int li = tid & 63;
    const bool loader = (a < 5);
    const size_t baseC  = (size_t)h * 64 + li;
    const size_t baseKV = (size_t)(h >> 2) * 64 + li;

    auto gload = [&](int t) -> float {
        switch (a) {
            case 0:  return g_r[(size_t)t * C_ + baseC];
            case 1: {
                float kv = g_k [(size_t)t * 512 + baseKV];
                float ew = g_ew[(size_t)t * C_ + baseC];
                return kv * (1.f - ew);
            }
            case 2:  return g_ew[(size_t)t * C_ + baseC];
            case 3:  return g_v [(size_t)t * 512 + baseKV];
            default: return g_gate[(size_t)t * C_ + baseC];
        }
    };

    float rr[8];
    if (loader) {
        #pragma unroll
        for (int p = 0; p < 8; p++) rr[p] = gload(p);
        sh[0][a * 64 + li] = rr[0];
    }
    __syncthreads();

    #pragma unroll 8
    for (int t = 0; t < T_; t++) {
        if (loader) {
            if (t + 8 < T_) rr[(t + 8) & 7] = gload(t + 8);
            if (t + 1 < T_) sh[(t + 1) & 1][a * 64 + li] = rr[(t + 1) & 7];
        }
        const float* S = sh[t & 1];

        float vv = S[3 * 64 + vcol];
        unsigned long long vv2;
        asm("mov.b64 %0, {%1, %1};" : "=l"(vv2) : "f"(vv));

        const bool reset = (nsh[t] != 0);

        const ulonglong2* rp = (const ulonglong2*)&S[0 * 64 + kg * 8];
        const ulonglong2* kp = (const ulonglong2*)&S[1 * 64 + kg * 8];
        const ulonglong2* wp = (const ulonglong2*)&S[2 * 64 + kg * 8];
        ulonglong2 rA = rp[0], rB = rp[1];
        ulonglong2 kA = kp[0], kB = kp[1];
        ulonglong2 wA = wp[0], wB = wp[1];
        unsigned long long r2[4] = { rA.x, rA.y, rB.x, rB.y };
        unsigned long long k2[4] = { kA.x, kA.y, kB.x, kB.y };
        unsigned long long w2[4] = { wA.x, wA.y, wB.x, wB.y };

        unsigned long long ps2 = 0ULL;
        #pragma unroll
        for (int j2 = 0; j2 < 4; j2++) {
            if (reset) s2[j2] = 0ULL;
            unsigned long long kv2;
            asm("mul.rn.f32x2 %0, %1, %2;"    : "=l"(kv2)    : "l"(k2[j2]), "l"(vv2));
            asm("fma.rn.f32x2 %0, %1, %2, %3;" : "=l"(s2[j2]) : "l"(s2[j2]), "l"(w2[j2]), "l"(kv2));
            asm("fma.rn.f32x2 %0, %1, %2, %0;" : "+l"(ps2)    : "l"(r2[j2]), "l"(s2[j2]));
        }

        float plo = __uint_as_float((unsigned)(ps2 & 0xffffffffULL));
        float phi = __uint_as_float((unsigned)(ps2 >> 32));
        float ps = plo + phi;
        ps += __shfl_xor_sync(0xffffffffu, ps, 1);
        ps += __shfl_xor_sync(0xffffffffu, ps, 2);
        ps += __shfl_xor_sync(0xffffffffu, ps, 4);
        if (kg == 0) {
            float gt = S[4 * 64 + vcol];
            g_out[(size_t)t * C_ + h * 64 + vcol] = ps * gt;
        }
        __syncthreads();
    }

    // final state
    #pragma unroll
    for (int j2 = 0; j2 < 4; j2++) {
        float slo = __uint_as_float((unsigned)(s2[j2] & 0xffffffffULL));
        float shi = __uint_as_float((unsigned)(s2[j2] >> 32));
        g_sfin[h * 4096 + (kg * 8 + 2 * j2) * 64 + vcol]     = slo;
        g_sfin[h * 4096 + (kg * 8 + 2 * j2 + 1) * 64 + vcol] = shi;
    }
}

// ---------------- new_state writer ----------------
__global__ void k_state(float* __restrict__ dout, const float* __restrict__ x,
                        const int* __restrict__ lenp)
{
    int idx = blockIdx.x * blockDim.x + threadIdx.x;
    int L = lenp ? lenp[0] : T_;
    if (idx < C_)
        dout[(size_t)T_ * C_ + idx] = x[(size_t)(L - 1) * C_ + idx];
    if (idx < H_ * S_ * S_)
        dout[(size_t)T_ * C_ + C_ + idx] = g_sfin[idx];
}

// ---------------- host-side orchestration ----------------
template <typename Sym>
static float* devaddr(Sym& sym) {
    void* p = nullptr;
    cudaGetSymbolAddress(&p, sym);
    return (float*)p;
}

extern "C" void kernel_launch(void* const* d_in, const int* in_sizes, int n_in,
                              void* d_out, int out_size)
{
    int i = 0;
    const float* x       = (const float*)d_in[i++];
    const float* state   = (const float*)d_in[i++];
    const unsigned char* ns = (const unsigned char*)d_in[i++];
    const int* lenp = nullptr;
    if (n_in >= 20) { lenp = (const int*)d_in[i++]; }
    const float* maa_x = (const float*)d_in[i++];
    const float* maa_r = (const float*)d_in[i++];
    const float* maa_k = (const float*)d_in[i++];
    const float* maa_v = (const float*)d_in[i++];
    const float* maa_w = (const float*)d_in[i++];
    const float* maa_g = (const float*)d_in[i++];
    const float* maa_w1 = (const float*)d_in[i++];  // [C, 160]
    const float* maa_w2 = (const float*)d_in[i++];  // [5, 32, C]
    const float* tdecay = (const float*)d_in[i++];  // [C]
    const float* dec_w1 = (const float*)d_in[i++];  // [C, 64]
    const float* dec_w2 = (const float*)d_in[i++];  // [64, C]
    const float* Wq = (const float*)d_in[i++];      // [C, C]
    const float* Wk = (const float*)d_in[i++];      // [C, 512]
    const float* Wv = (const float*)d_in[i++];      // [C, 512]
    const float* Wg = (const float*)d_in[i++];      // [C, C]
    const float* Wo = (const float*)d_in[i++];      // [C, C]
    float* dout = (float*)d_out;

    float* p_sx   = devaddr(g_sx);
    float* p_xxx  = devaddr(g_xxx);
    float* p_t1   = devaddr(g_t1);
    float* p_xr   = devaddr(g_xr);
    float* p_xk   = devaddr(g_xk);
    float* p_xv   = devaddr(g_xv);
    float* p_xw   = devaddr(g_xw);
    float* p_xg   = devaddr(g_xg);
    float* p_r    = devaddr(g_r);
    float* p_k    = devaddr(g_k);
    float* p_v    = devaddr(g_v);
    float* p_t2   = devaddr(g_t2);
    float* p_ew   = devaddr(g_ew);
    float* p_gate = devaddr(g_gate);
    float* p_out  = devaddr(g_out);
    float* p_part = devaddr(g_part);

    const int EW = 256;
    const int GE = (T_ * C_ + EW - 1) / EW;
    dim3 blk(256);

    // 1) token shift + xxx
    k_shift<<<GE, EW>>>(x, state, ns, maa_x);

    // 2) t1 partials (split-K 8): xxx[2048,2048] @ maa_w1[2048,160]
    {
        Batch bt = {};
        const int KCH = C_ / SPLITK;      // 256
        for (int z = 0; z < SPLITK; z++) {
            bt.A[z]  = p_xxx + z * KCH;
            bt.B[z]  = maa_w1 + (size_t)z * KCH * (5 * LMAA_);
            bt.Cc[z] = p_part + (size_t)z * T_ * (5 * LMAA_);
            bt.vec[z] = nullptr;
        }
        dim3 g(2, T_ / 128, SPLITK);
        gemm128<EPI_NONE><<<g, blk>>>(bt, C_, 5 * LMAA_, 5 * LMAA_, 5 * LMAA_, KCH,
                                      nullptr, nullptr);
        int n = T_ * 5 * LMAA_;
        k_red_tanh<<<(n + EW - 1) / EW, EW>>>(p_part, p_t1, n, n);
    }

    // 3) batched mix (z=5): xb = x + sx*(maa_b + t1[:,z]@w2[z])
    {
        Batch bt = {};
        const float* vecs[5] = { maa_r, maa_k, maa_v, maa_w, maa_g };
        float* outs[5] = { p_xr, p_xk, p_xv, p_xw, p_xg };
        for (int z = 0; z < 5; z++) {
            bt.A[z]  = p_t1 + z * LMAA_;
            bt.B[z]  = maa_w2 + (size_t)z * LMAA_ * C_;
            bt.Cc[z] = outs[z];
            bt.vec[z] = vecs[z];
        }
        dim3 g(C_ / 128, T_ / 128, 5);
        gemm128<EPI_MIX><<<g, blk>>>(bt, 5 * LMAA_, C_, C_, C_, LMAA_, x, p_sx);
    }

    // 4) r projection: xr @ Wq
    {
        Batch bt = {}; bt.A[0] = p_xr; bt.B[0] = Wq; bt.Cc[0] = p_r; bt.vec[0] = nullptr;
        dim3 g(C_ / 128, T_ / 128, 1);
        gemm128<EPI_NONE><<<g, blk>>>(bt, C_, C_, C_, C_, C_, nullptr, nullptr);
    }
    // 5) k/v projections (z=2 batched)
    {
        Batch bt = {};
        bt.A[0] = p_xk; bt.B[0] = Wk; bt.Cc[0] = p_k; bt.vec[0] = nullptr;
        bt.A[1] = p_xv; bt.B[1] = Wv; bt.Cc[1] = p_v; bt.vec[1] = nullptr;
        dim3 g((HKV_ * S_) / 128, T_ / 128, 2);
        gemm128<EPI_NONE><<<g, blk>>>(bt, C_, HKV_ * S_, HKV_ * S_, HKV_ * S_, C_,
                                      nullptr, nullptr);
    }
    // 6) decay LoRA stage 1 (split-K 8): t2 = tanh(xw @ dec_w1)
    {
        Batch bt = {};
        const int KCH = C_ / SPLITK;
        for (int z = 0; z < SPLITK; z++) {
            bt.A[z]  = p_xw + z * KCH;
            bt.B[z]  = dec_w1 + (size_t)z * KCH * LDEC_;
            bt.Cc[z] = p_part + (size_t)z * T_ * LDEC_;
            bt.vec[z] = nullptr;
        }
        dim3 g(1, T_ / 128, SPLITK);
        gemm128<EPI_NONE><<<g, blk>>>(bt, C_, LDEC_, LDEC_, LDEC_, KCH, nullptr, nullptr);
        int n = T_ * LDEC_;
        k_red_tanh<<<(n + EW - 1) / EW, EW>>>(p_part, p_t2, n, n);
    }
    // 7) decay LoRA stage 2: ew = exp(max(-exp(t2@dec_w2 + tdecay), -5))
    {
        Batch bt = {}; bt.A[0] = p_t2; bt.B[0] = dec_w2; bt.Cc[0] = p_ew; bt.vec[0] = tdecay;
        dim3 g(C_ / 128, T_ / 128, 1);
        gemm128<EPI_DECAY><<<g, blk>>>(bt, LDEC_, C_, C_, C_, LDEC_, nullptr, nullptr);
    }
    // 8) gate = sigmoid(xg @ Wg)
    {
        Batch bt = {}; bt.A[0] = p_xg; bt.B[0] = Wg; bt.Cc[0] = p_gate; bt.vec[0] = nullptr;
        dim3 g(C_ / 128, T_ / 128, 1);
        gemm128<EPI_SIG><<<g, blk>>>(bt, C_, C_, C_, C_, C_, nullptr, nullptr);
    }
    // 9) sequential scan (keff + gate fused inside)
    k_scan<<<H_, 512>>>(state, ns);
    // 10) final projection: dout = (out*gate) @ Wo
    {
        Batch bt = {}; bt.A[0] = p_out; bt.B[0] = Wo; bt.Cc[0] = dout; bt.vec[0] = nullptr;
        dim3 g(C_ / 128, T_ / 128, 1);
        gemm128<EPI_NONE><<<g, blk>>>(bt, C_, C_, C_, C_, C_, nullptr, nullptr);
    }
    // 11) new_state (only if the harness expects both outputs)
    if (out_size >= T_ * C_ + (S_ + 1) * C_) {
        int n = H_ * S_ * S_;
        k_state<<<(n + EW - 1) / EW, EW>>>(dout, x, lenp);
    }
}

// round 7
// speedup vs baseline: 1.9747x; 1.4543x over previous
#include <cuda_runtime.h>
#include <cuda_bf16.h>
#include <math.h>
#include <stdint.h>

#define T_ 2048
#define C_ 2048
#define H_ 32
#define S_ 64
#define HKV_ 8
#define LMAA_ 32
#define LDEC_ 64
#define K3_ (3 * C_)   // 6144

// ---------------- scratch (static device arrays; no runtime alloc) ----------------
__device__ float g_sx [T_*C_];
__device__ float g_xxx[T_*C_];
__device__ float g_t1 [T_*5*LMAA_];
__device__ float g_xr [T_*C_];
__device__ float g_xk [T_*C_];
__device__ float g_xv [T_*C_];
__device__ float g_xw [T_*C_];
__device__ float g_xg [T_*C_];
__device__ float g_r  [T_*C_];
__device__ float g_k  [T_*HKV_*S_];
__device__ float g_v  [T_*HKV_*S_];
__device__ float g_t2 [T_*LDEC_];
__device__ float g_ew [T_*C_];
__device__ float g_gate[T_*C_];
__device__ float g_out[T_*C_];
__device__ float g_sfin[H_*S_*S_];

// bf16 3-split buffers (A' = [hi|hi|lo], W' = [hi|lo|hi] so A'.W'^T = hh+hl+lh)
__device__ __align__(128) __nv_bfloat16 g_ba0[(size_t)T_ * K3_];
__device__ __align__(128) __nv_bfloat16 g_ba1[(size_t)T_ * K3_];
__device__ __align__(128) __nv_bfloat16 g_ba2[(size_t)T_ * K3_];
__device__ __align__(128) __nv_bfloat16 g_bw0[(size_t)2048 * K3_];
__device__ __align__(128) __nv_bfloat16 g_bw1[(size_t)512 * K3_];
__device__ __align__(128) __nv_bfloat16 g_bw2[(size_t)512 * K3_];
__device__ __align__(128) __nv_bfloat16 g_bws[(size_t)256 * K3_];

// ---------------- epilogue ids ----------------
#define EPI_NONE  0
#define EPI_TANH  1
#define EPI_SIG   2
#define EPI_MIX   3
#define EPI_DECAY 4

// ---------------- mma.sync helpers (sm_80+ PTX; works on plain sm_103 target) ----
__device__ __forceinline__ uint32_t smem_u32(const void* p) {
    uint32_t a;
    asm("{ .reg .u64 t; cvta.to.shared.u64 t, %1; cvt.u32.u64 %0, t; }" : "=r"(a) : "l"(p));
    return a;
}
__device__ __forceinline__ void cp_async16(uint32_t saddr, const void* g) {
    asm volatile("cp.async.cg.shared.global [%0], [%1], 16;" :: "r"(saddr), "l"(g) : "memory");
}
__device__ __forceinline__ void ldmatrix_x4(uint32_t* r, uint32_t addr) {
    asm volatile("ldmatrix.sync.aligned.m8n8.x4.shared.b16 {%0,%1,%2,%3}, [%4];"
        : "=r"(r[0]), "=r"(r[1]), "=r"(r[2]), "=r"(r[3]) : "r"(addr));
}
__device__ __forceinline__ void mma16816(float* c, const uint32_t* a, uint32_t b0, uint32_t b1) {
    asm volatile("mma.sync.aligned.m16n8k16.row.col.f32.bf16.bf16.f32 "
        "{%0,%1,%2,%3}, {%4,%5,%6,%7}, {%8,%9}, {%0,%1,%2,%3};"
        : "+f"(c[0]), "+f"(c[1]), "+f"(c[2]), "+f"(c[3])
        : "r"(a[0]), "r"(a[1]), "r"(a[2]), "r"(a[3]), "r"(b0), "r"(b1));
}

struct TBatch {
    const __nv_bfloat16* A[2];
    const __nv_bfloat16* B[2];
    float*               Cc[2];
};

// ---------------- HMMA bf16 GEMM: C[M,N] = A'[M,K3] @ B'[N,K3]^T ----------------
// 128x128 CTA tile, 8 warps (2m x 4n), each warp 64x32 via m16n8k16.
// BK=64, 3-stage cp.async pipeline, SW128-xor swizzled smem, ldmatrix.x4.
template<int EPI>
__global__ __launch_bounds__(256, 2)
void hgemm(TBatch bt, int N, int ldc)
{
    extern __shared__ char smem[];
    const uint32_t sbase = smem_u32(smem);   // 3 stages x (A 16KB | B 16KB)

    const int z = blockIdx.z;
    const __nv_bfloat16* __restrict__ Ag = bt.A[z];
    const __nv_bfloat16* __restrict__ Bg = bt.B[z];
    float* __restrict__ Cg = bt.Cc[z];

    const int tid  = threadIdx.x;
    const int lane = tid & 31;
    const int wid  = tid >> 5;
    const int wm   = wid >> 2;    // 0..1
    const int wn   = wid & 3;     // 0..3
    const int bx = blockIdx.x, by = blockIdx.y;

    float acc[4][4][4];
    #pragma unroll
    for (int i = 0; i < 4; i++)
        #pragma unroll
        for (int j = 0; j < 4; j++)
            #pragma unroll
            for (int k = 0; k < 4; k++) acc[i][j][k] = 0.f;

    const __nv_bfloat16* Abase = Ag + (size_t)(by * 128) * K3_;
    const __nv_bfloat16* Bbase = Bg + (size_t)(bx * 128) * K3_;

    // stage loader: 128 rows x 64 bf16 (128B) per operand, 16B per cp.async
    auto load_stage = [&](int kt, int s) {
        const uint32_t sa = sbase + s * 32768;
        const __nv_bfloat16* Agk = Abase + kt * 64;
        const __nv_bfloat16* Bgk = Bbase + kt * 64;
        #pragma unroll
        for (int q = 0; q < 4; q++) {
            const int c = q * 256 + tid;
            const int row = c >> 3, j = c & 7;
            uint32_t off = (uint32_t)(row * 128 + j * 16);
            off ^= (off >> 3) & 0x70;
            cp_async16(sa + off,         Agk + (size_t)row * K3_ + j * 8);
            cp_async16(sa + 16384 + off, Bgk + (size_t)row * K3_ + j * 8);
        }
        asm volatile("cp.async.commit_group;" ::: "memory");
    };

    // per-lane fragment bases (unswizzled byte offsets within a 16KB tile)
    const int a_roff = (wm * 64 + (lane & 15)) * 128 + (lane >> 4) * 16;
    const int b_roff = (wn * 32 + (lane & 7) + ((lane >> 4) << 3)) * 128 + ((lane >> 3) & 1) * 16;

    auto compute = [&](int s) {
        const uint32_t sa = sbase + s * 32768;
        const uint32_t sbb = sa + 16384;
        #pragma unroll
        for (int ks = 0; ks < 4; ks++) {
            uint32_t af[4][4];
            #pragma unroll
            for (int mt = 0; mt < 4; mt++) {
                uint32_t off = (uint32_t)(a_roff + mt * 16 * 128 + ks * 32);
                off ^= (off >> 3) & 0x70;
                ldmatrix_x4(af[mt], sa + off);
            }
            uint32_t bf2[2][4];
            #pragma unroll
            for (int nt2 = 0; nt2 < 2; nt2++) {
                uint32_t off = (uint32_t)(b_roff + nt2 * 16 * 128 + ks * 32);
                off ^= (off >> 3) & 0x70;
                ldmatrix_x4(bf2[nt2], sbb + off);
            }
            #pragma unroll
            for (int mt = 0; mt < 4; mt++)
                #pragma unroll
                for (int nt = 0; nt < 4; nt++)
                    mma16816(acc[mt][nt], af[mt],
                             bf2[nt >> 1][(nt & 1) * 2], bf2[nt >> 1][(nt & 1) * 2 + 1]);
        }
    };

    const int nk = K3_ >> 6;   // 96
    load_stage(0, 0);
    load_stage(1, 1);

    for (int kt = 0; kt < nk; kt++) {
        asm volatile("cp.async.wait_group 1;" ::: "memory");
        __syncthreads();
        if (kt + 2 < nk) load_stage(kt + 2, (kt + 2) % 3);
        else asm volatile("cp.async.commit_group;" ::: "memory");
        compute(kt % 3);
    }

    // epilogue
    #pragma unroll
    for (int mt = 0; mt < 4; mt++) {
        #pragma unroll
        for (int hrow = 0; hrow < 2; hrow++) {
            const int row = by * 128 + wm * 64 + mt * 16 + hrow * 8 + (lane >> 2);
            float* crow = Cg + (size_t)row * ldc;
            #pragma unroll
            for (int nt = 0; nt < 4; nt++) {
                const int col = bx * 128 + wn * 32 + nt * 8 + (lane & 3) * 2;
                if (col >= N) continue;
                float v0 = acc[mt][nt][hrow * 2 + 0];
                float v1 = acc[mt][nt][hrow * 2 + 1];
                if (EPI == EPI_TANH) { v0 = tanhf(v0); v1 = tanhf(v1); }
                if (EPI == EPI_SIG)  { v0 = 1.f/(1.f+expf(-v0)); v1 = 1.f/(1.f+expf(-v1)); }
                *(float2*)&crow[col] = make_float2(v0, v1);
            }
        }
    }
}

// ---------------- bf16 split conversions ----------------
// activations: src[M x 2048] f32 -> dst[M x 6144] bf16 as [hi | hi | lo]
__global__ void k_conv_act(const float* __restrict__ src, __nv_bfloat16* __restrict__ dst)
{
    int idx = blockIdx.x * blockDim.x + threadIdx.x;
    if (idx >= T_ * C_) return;
    int row = idx >> 11;
    int k = idx & 2047;
    float a = src[idx];
    __nv_bfloat16 hi = __float2bfloat16(a);
    __nv_bfloat16 lo = __float2bfloat16(a - __bfloat162float(hi));
    size_t base = (size_t)row * K3_;
    dst[base + k] = hi;
    dst[base + C_ + k] = hi;
    dst[base + 2 * C_ + k] = lo;
}

// weights: src[2048 x N] f32 -> dst[Npad x 6144] bf16 as rows n: [hi | lo | hi], transposed
__global__ void k_conv_w(const float* __restrict__ src, __nv_bfloat16* __restrict__ dst, int N)
{
    __shared__ float tile[32][33];
    const int n0 = blockIdx.x * 32;
    const int k0 = blockIdx.y * 32;
    const int tx = threadIdx.x, ty = threadIdx.y;  // (32, 8)
    #pragma unroll
    for (int yy = 0; yy < 32; yy += 8) {
        int n = n0 + tx, k = k0 + ty + yy;
        tile[ty + yy][tx] = (n < N) ? src[(size_t)k * N + n] : 0.f;
    }
    __syncthreads();
    #pragma unroll
    for (int yy = 0; yy < 32; yy += 8) {
        int n = n0 + ty + yy;
        int k = k0 + tx;
        float a = tile[tx][ty + yy];
        __nv_bfloat16 hi = __float2bfloat16(a);
        __nv_bfloat16 lo = __float2bfloat16(a - __bfloat162float(hi));
        size_t base = (size_t)n * K3_;
        dst[base + k] = hi;
        dst[base + C_ + k] = lo;
        dst[base + 2 * C_ + k] = hi;
    }
}

// ---------------- FFMA2 GEMM (small-K: MIX K=32, DECAY K=64) ----------------
struct Batch {
    const float* A[8];
    const float* B[8];
    float*       Cc[8];
    const float* vec[8];
};

template<int EPI>
__device__ __forceinline__ float epi_apply(float a, size_t idx, int col,
    const float* __restrict__ aux1, const float* __restrict__ aux2,
    const float* __restrict__ vec)
{
    if (EPI == EPI_MIX)   return aux1[idx] + aux2[idx] * (vec[col] + a);
    if (EPI == EPI_DECAY) { float lw = fmaxf(-expf(a + vec[col]), -5.0f); return expf(lw); }
    return a;
}

template<int EPI>
__global__ __launch_bounds__(256, 2)
void gemm128(Batch bt, int lda, int ldb, int ldc, int N, int K,
             const float* __restrict__ aux1, const float* __restrict__ aux2)
{
    __shared__ float2 As[2][16][128];
    __shared__ float  Bs[2][16][128];

    const int z = blockIdx.z;
    const float* __restrict__ A   = bt.A[z];
    const float* __restrict__ B   = bt.B[z];
    float*       __restrict__ C   = bt.Cc[z];
    const float* __restrict__ vec = bt.vec[z];

    const int tid = threadIdx.x;
    const int bx = blockIdx.x, by = blockIdx.y;
    const int arow = tid >> 1,  acol = (tid & 1) * 8;
    const int brow = tid >> 4,  bcol = (tid & 15) * 8;
    const int tx = tid & 15,    ty = tid >> 4;

    unsigned long long acc[8][4];
    #pragma unroll
    for (int i = 0; i < 8; i++)
        #pragma unroll
        for (int j = 0; j < 4; j++) acc[i][j] = 0ULL;

    const float* Ap = A + (size_t)(by * 128 + arow) * lda + acol;
    const int gcolb = bx * 128 + bcol;

    float4 a0, a1, b0, b1;
    auto loadAB = [&](int k0) {
        a0 = *(const float4*)(Ap + k0);
        a1 = *(const float4*)(Ap + k0 + 4);
        const float* bp = B + (size_t)(k0 + brow) * ldb + gcolb;
        if (gcolb + 7 < N) {
            b0 = *(const float4*)bp;
            b1 = *(const float4*)(bp + 4);
        } else {
            float t[8];
            #pragma unroll
            for (int j = 0; j < 8; j++) t[j] = (gcolb + j < N) ? bp[j] : 0.f;
            b0 = make_float4(t[0], t[1], t[2], t[3]);
            b1 = make_float4(t[4], t[5], t[6], t[7]);
        }
    };
    auto storeAB = [&](int buf) {
        As[buf][acol + 0][arow] = make_float2(a0.x, a0.x);
        As[buf][acol + 1][arow] = make_float2(a0.y, a0.y);
        As[buf][acol + 2][arow] = make_float2(a0.z, a0.z);
        As[buf][acol + 3][arow] = make_float2(a0.w, a0.w);
        As[buf][acol + 4][arow] = make_float2(a1.x, a1.x);
        As[buf][acol + 5][arow] = make_float2(a1.y, a1.y);
        As[buf][acol + 6][arow] = make_float2(a1.z, a1.z);
        As[buf][acol + 7][arow] = make_float2(a1.w, a1.w);
        *(float4*)&Bs[buf][brow][bcol]     = b0;
        *(float4*)&Bs[buf][brow][bcol + 4] = b1;
    };

    loadAB(0);
    storeAB(0);
    __syncthreads();

    const int nt = K >> 4;
    for (int kt = 0; kt < nt; kt++) {
        const int cur = kt & 1;
        if (kt + 1 < nt) loadAB((kt + 1) << 4);

        #pragma unroll
        for (int kk = 0; kk < 16; kk++) {
            unsigned long long a2[8], b2[4];
            const ulonglong2* ap = (const ulonglong2*)&As[cur][kk][ty * 8];
            ulonglong2 w;
            w = ap[0]; a2[0] = w.x; a2[1] = w.y;
            w = ap[1]; a2[2] = w.x; a2[3] = w.y;
            w = ap[2]; a2[4] = w.x; a2[5] = w.y;
            w = ap[3]; a2[6] = w.x; a2[7] = w.y;
            const ulonglong2* bp2 = (const ulonglong2*)&Bs[cur][kk][tx * 8];
            w = bp2[0]; b2[0] = w.x; b2[1] = w.y;
            w = bp2[1]; b2[2] = w.x; b2[3] = w.y;
            #pragma unroll
            for (int i = 0; i < 8; i++)
                #pragma unroll
                for (int j = 0; j < 4; j++)
                    asm("fma.rn.f32x2 %0, %1, %2, %0;"
                        : "+l"(acc[i][j]) : "l"(a2[i]), "l"(b2[j]));
        }

        if (kt + 1 < nt) storeAB(cur ^ 1);
        __syncthreads();
    }

    #pragma unroll
    for (int i = 0; i < 8; i++) {
        const int row = by * 128 + ty * 8 + i;
        float* crow = C + (size_t)row * ldc;
        #pragma unroll
        for (int j = 0; j < 4; j++) {
            const int col = bx * 128 + tx * 8 + 2 * j;
            if (col >= N) continue;
            float lo = __uint_as_float((unsigned)(acc[i][j] & 0xffffffffULL));
            float hi = __uint_as_float((unsigned)(acc[i][j] >> 32));
            size_t idx = (size_t)row * ldc + col;
            lo = epi_apply<EPI>(lo, idx, col, aux1, aux2, vec);
            if (col + 1 < N) {
                hi = epi_apply<EPI>(hi, idx + 1, col + 1, aux1, aux2, vec);
                *(float2*)&crow[col] = make_float2(lo, hi);
            } else {
                crow[col] = lo;
            }
        }
    }
}

// ---------------- elementwise: token shift ----------------
__global__ void k_shift(const float* __restrict__ x, const float* __restrict__ state,
                        const unsigned char* __restrict__ ns,
                        const float* __restrict__ maa_x)
{
    int idx = blockIdx.x * blockDim.x + threadIdx.x;
    if (idx >= T_ * C_) return;
    int t = idx >> 11;
    int c = idx & 2047;
    float prev = (t == 0) ? state[c] : x[idx - C_];
    if (ns[t]) prev = 0.f;
    float s = prev - x[idx];
    g_sx[idx]  = s;
    g_xxx[idx] = x[idx] + s * maa_x[c];
}

// ---------------- the RWKV scan ----------------
__global__ __launch_bounds__(512)
void k_scan(const float* __restrict__ state, const unsigned char* __restrict__ ns)
{
    const int h = blockIdx.x;
    const int tid = threadIdx.x;
    const int vcol = tid >> 3;
    const int kg = tid & 7;

    unsigned long long s2[4];
    #pragma unroll
    for (int j2 = 0; j2 < 4; j2++) {
        float slo = state[C_ + h * 4096 + (kg * 8 + 2 * j2) * 64 + vcol];
        float shi = state[C_ + h * 4096 + (kg * 8 + 2 * j2 + 1) * 64 + vcol];
        asm("mov.b64 %0, {%1, %2};" : "=l"(s2[j2]) : "f"(slo), "f"(shi));
    }

    __shared__ float sh[2][5 * 64];
    __shared__ unsigned char nsh[T_];
    for (int i = tid; i < T_; i += 512) nsh[i] = ns[i];

    const int a  = tid >> 6;
    const int li = tid & 63;
    const bool loader = (a < 5);
    const size_t baseC  = (size_t)h * 64 + li;
    const size_t baseKV = (size_t)(h >> 2) * 64 + li;

    auto gload = [&](int t) -> float {
        switch (a) {
            case 0:  return g_r[(size_t)t * C_ + baseC];
            case 1: {
                float kv = g_k [(size_t)t * 512 + baseKV];
                float ew = g_ew[(size_t)t * C_ + baseC];
                return kv * (1.f - ew);
            }
            case 2:  return g_ew[(size_t)t * C_ + baseC];
            case 3:  return g_v [(size_t)t * 512 + baseKV];
            default: return g_gate[(size_t)t * C_ + baseC];
        }
    };

    float rr[8];
    if (loader) {
        #pragma unroll
        for (int p = 0; p < 8; p++) rr[p] = gload(p);
        sh[0][a * 64 + li] = rr[0];
    }
    __syncthreads();

    #pragma unroll 8
    for (int t = 0; t < T_; t++) {
        if (loader) {
            if (t + 8 < T_) rr[(t + 8) & 7] = gload(t + 8);
            if (t + 1 < T_) sh[(t + 1) & 1][a * 64 + li] = rr[(t + 1) & 7];
        }
        const float* S = sh[t & 1];

        float vv = S[3 * 64 + vcol];
        unsigned long long vv2;
        asm("mov.b64 %0, {%1, %1};" : "=l"(vv2) : "f"(vv));

        const bool reset = (nsh[t] != 0);

        const ulonglong2* rp = (const ulonglong2*)&S[0 * 64 + kg * 8];
        const ulonglong2* kp = (const ulonglong2*)&S[1 * 64 + kg * 8];
        const ulonglong2* wp = (const ulonglong2*)&S[2 * 64 + kg * 8];
        ulonglong2 rA = rp[0], rB = rp[1];
        ulonglong2 kA = kp[0], kB = kp[1];
        ulonglong2 wA = wp[0], wB = wp[1];
        unsigned long long r2[4] = { rA.x, rA.y, rB.x, rB.y };
        unsigned long long k2[4] = { kA.x, kA.y, kB.x, kB.y };
        unsigned long long w2[4] = { wA.x, wA.y, wB.x, wB.y };

        unsigned long long ps2 = 0ULL;
        #pragma unroll
        for (int j2 = 0; j2 < 4; j2++) {
            if (reset) s2[j2] = 0ULL;
            unsigned long long kv2;
            asm("mul.rn.f32x2 %0, %1, %2;"     : "=l"(kv2)    : "l"(k2[j2]), "l"(vv2));
            asm("fma.rn.f32x2 %0, %1, %2, %3;" : "=l"(s2[j2]) : "l"(s2[j2]), "l"(w2[j2]), "l"(kv2));
            asm("fma.rn.f32x2 %0, %1, %2, %0;" : "+l"(ps2)    : "l"(r2[j2]), "l"(s2[j2]));
        }

        float plo = __uint_as_float((unsigned)(ps2 & 0xffffffffULL));
        float phi = __uint_as_float((unsigned)(ps2 >> 32));
        float ps = plo + phi;
        ps += __shfl_xor_sync(0xffffffffu, ps, 1);
        ps += __shfl_xor_sync(0xffffffffu, ps, 2);
        ps += __shfl_xor_sync(0xffffffffu, ps, 4);
        if (kg == 0) {
            float gt = S[4 * 64 + vcol];
            g_out[(size_t)t * C_ + h * 64 + vcol] = ps * gt;
        }
        __syncthreads();
    }

    #pragma unroll
    for (int j2 = 0; j2 < 4; j2++) {
        float slo = __uint_as_float((unsigned)(s2[j2] & 0xffffffffULL));
        float shi = __uint_as_float((unsigned)(s2[j2] >> 32));
        g_sfin[h * 4096 + (kg * 8 + 2 * j2) * 64 + vcol]     = slo;
        g_sfin[h * 4096 + (kg * 8 + 2 * j2 + 1) * 64 + vcol] = shi;
    }
}

// ---------------- new_state writer ----------------
__global__ void k_state(float* __restrict__ dout, const float* __restrict__ x,
                        const int* __restrict__ lenp)
{
    int idx = blockIdx.x * blockDim.x + threadIdx.x;
    int L = lenp ? lenp[0] : T_;
    if (idx < C_)
        dout[(size_t)T_ * C_ + idx] = x[(size_t)(L - 1) * C_ + idx];
    if (idx < H_ * S_ * S_)
        dout[(size_t)T_ * C_ + C_ + idx] = g_sfin[idx];
}

// ---------------- host-side orchestration ----------------
template <typename Sym>
static void* devaddr_v(Sym& sym) {
    void* p = nullptr;
    cudaGetSymbolAddress(&p, sym);
    return p;
}

#define HG_SMEM (3 * 32768)

extern "C" void kernel_launch(void* const* d_in, const int* in_sizes, int n_in,
                              void* d_out, int out_size)
{
    int i = 0;
    const float* x       = (const float*)d_in[i++];
    const float* state   = (const float*)d_in[i++];
    const unsigned char* ns = (const unsigned char*)d_in[i++];
    const int* lenp = nullptr;
    if (n_in >= 20) { lenp = (const int*)d_in[i++]; }
    const float* maa_x = (const float*)d_in[i++];
    const float* maa_r = (const float*)d_in[i++];
    const float* maa_k = (const float*)d_in[i++];
    const float* maa_v = (const float*)d_in[i++];
    const float* maa_w = (const float*)d_in[i++];
    const float* maa_g = (const float*)d_in[i++];
    const float* maa_w1 = (const float*)d_in[i++];  // [C, 160]
    const float* maa_w2 = (const float*)d_in[i++];  // [5, 32, C]
    const float* tdecay = (const float*)d_in[i++];  // [C]
    const float* dec_w1 = (const float*)d_in[i++];  // [C, 64]
    const float* dec_w2 = (const float*)d_in[i++];  // [64, C]
    const float* Wq = (const float*)d_in[i++];      // [C, C]
    const float* Wk = (const float*)d_in[i++];      // [C, 512]
    const float* Wv = (const float*)d_in[i++];      // [C, 512]
    const float* Wg = (const float*)d_in[i++];      // [C, C]
    const float* Wo = (const float*)d_in[i++];      // [C, C]
    float* dout = (float*)d_out;

    float* p_sx   = (float*)devaddr_v(g_sx);
    float* p_xxx  = (float*)devaddr_v(g_xxx);
    float* p_t1   = (float*)devaddr_v(g_t1);
    float* p_xr   = (float*)devaddr_v(g_xr);
    float* p_xk   = (float*)devaddr_v(g_xk);
    float* p_xv   = (float*)devaddr_v(g_xv);
    float* p_xw   = (float*)devaddr_v(g_xw);
    float* p_xg   = (float*)devaddr_v(g_xg);
    float* p_r    = (float*)devaddr_v(g_r);
    float* p_k    = (float*)devaddr_v(g_k);
    float* p_v    = (float*)devaddr_v(g_v);
    float* p_t2   = (float*)devaddr_v(g_t2);
    float* p_ew   = (float*)devaddr_v(g_ew);
    float* p_gate = (float*)devaddr_v(g_gate);
    float* p_out  = (float*)devaddr_v(g_out);
    __nv_bfloat16* p_ba0 = (__nv_bfloat16*)devaddr_v(g_ba0);
    __nv_bfloat16* p_ba1 = (__nv_bfloat16*)devaddr_v(g_ba1);
    __nv_bfloat16* p_ba2 = (__nv_bfloat16*)devaddr_v(g_ba2);
    __nv_bfloat16* p_bw0 = (__nv_bfloat16*)devaddr_v(g_bw0);
    __nv_bfloat16* p_bw1 = (__nv_bfloat16*)devaddr_v(g_bw1);
    __nv_bfloat16* p_bw2 = (__nv_bfloat16*)devaddr_v(g_bw2);
    __nv_bfloat16* p_bws = (__nv_bfloat16*)devaddr_v(g_bws);

    cudaFuncSetAttribute(hgemm<EPI_NONE>, cudaFuncAttributeMaxDynamicSharedMemorySize, HG_SMEM);
    cudaFuncSetAttribute(hgemm<EPI_TANH>, cudaFuncAttributeMaxDynamicSharedMemorySize, HG_SMEM);
    cudaFuncSetAttribute(hgemm<EPI_SIG>,  cudaFuncAttributeMaxDynamicSharedMemorySize, HG_SMEM);

    const int EW = 256;
    const int GE = (T_ * C_ + EW - 1) / EW;
    dim3 blk(256);
    dim3 cw(32, 8);

    // 1) token shift + xxx
    k_shift<<<GE, EW>>>(x, state, ns, maa_x);

    // 2) t1 = tanh(xxx @ maa_w1)  [T,160] (N padded to 256 in weight buffer)
    k_conv_act<<<GE, EW>>>(p_xxx, p_ba0);
    k_conv_w<<<dim3(256 / 32, 64), cw>>>(maa_w1, p_bws, 5 * LMAA_);
    {
        TBatch tb = {}; tb.A[0] = p_ba0; tb.B[0] = p_bws; tb.Cc[0] = p_t1;
        hgemm<EPI_TANH><<<dim3(2, 16, 1), blk, HG_SMEM>>>(tb, 5 * LMAA_, 5 * LMAA_);
    }

    // 3) batched mix (FFMA2, K=32): xb = x + sx*(maa_b + t1[:,z]@w2[z])
    {
        Batch bt = {};
        const float* vecs[5] = { maa_r, maa_k, maa_v, maa_w, maa_g };
        float* outs[5] = { p_xr, p_xk, p_xv, p_xw, p_xg };
        for (int z = 0; z < 5; z++) {
            bt.A[z]  = p_t1 + z * LMAA_;
            bt.B[z]  = maa_w2 + (size_t)z * LMAA_ * C_;
            bt.Cc[z] = outs[z];
            bt.vec[z] = vecs[z];
        }
        gemm128<EPI_MIX><<<dim3(C_ / 128, T_ / 128, 5), blk>>>(bt, 5 * LMAA_, C_, C_, C_, LMAA_, x, p_sx);
    }

    // 4) r = xr @ Wq
    k_conv_act<<<GE, EW>>>(p_xr, p_ba0);
    k_conv_w<<<dim3(C_ / 32, 64), cw>>>(Wq, p_bw0, C_);
    {
        TBatch tb = {}; tb.A[0] = p_ba0; tb.B[0] = p_bw0; tb.Cc[0] = p_r;
        hgemm<EPI_NONE><<<dim3(16, 16, 1), blk, HG_SMEM>>>(tb, C_, C_);
    }

    // 5) k/v projections (z=2)
    k_conv_act<<<GE, EW>>>(p_xk, p_ba1);
    k_conv_act<<<GE, EW>>>(p_xv, p_ba2);
    k_conv_w<<<dim3(512 / 32, 64), cw>>>(Wk, p_bw1, HKV_ * S_);
    k_conv_w<<<dim3(512 / 32, 64), cw>>>(Wv, p_bw2, HKV_ * S_);
    {
        TBatch tb = {};
        tb.A[0] = p_ba1; tb.B[0] = p_bw1; tb.Cc[0] = p_k;
        tb.A[1] = p_ba2; tb.B[1] = p_bw2; tb.Cc[1] = p_v;
        hgemm<EPI_NONE><<<dim3(4, 16, 2), blk, HG_SMEM>>>(tb, HKV_ * S_, HKV_ * S_);
    }

    // 6) t2 = tanh(xw @ dec_w1)  [T,64] (N padded to 128)
    k_conv_act<<<GE, EW>>>(p_xw, p_ba0);
    k_conv_w<<<dim3(128 / 32, 64), cw>>>(dec_w1, p_bws, LDEC_);
    {
        TBatch tb = {}; tb.A[0] = p_ba0; tb.B[0] = p_bws; tb.Cc[0] = p_t2;
        hgemm<EPI_TANH><<<dim3(1, 16, 1), blk, HG_SMEM>>>(tb, LDEC_, LDEC_);
    }

    // 7) ew = exp(max(-exp(t2@dec_w2 + tdecay), -5))  (FFMA2, K=64)
    {
        Batch bt = {}; bt.A[0] = p_t2; bt.B[0] = dec_w2; bt.Cc[0] = p_ew; bt.vec[0] = tdecay;
        gemm128<EPI_DECAY><<<dim3(C_ / 128, T_ / 128, 1), blk>>>(bt, LDEC_, C_, C_, C_, LDEC_, nullptr, nullptr);
    }

    // 8) gate = sigmoid(xg @ Wg)
    k_conv_act<<<GE, EW>>>(p_xg, p_ba0);
    k_conv_w<<<dim3(C_ / 32, 64), cw>>>(Wg, p_bw0, C_);
    {
        TBatch tb = {}; tb.A[0] = p_ba0; tb.B[0] = p_bw0; tb.Cc[0] = p_gate;
        hgemm<EPI_SIG><<<dim3(16, 16, 1), blk, HG_SMEM>>>(tb, C_, C_);
    }

    // 9) sequential scan (keff + gate fused inside)
    k_scan<<<H_, 512>>>(state, ns);

    // 10) final projection: dout = (out*gate) @ Wo
    k_conv_act<<<GE, EW>>>(p_out, p_ba0);
    k_conv_w<<<dim3(C_ / 32, 64), cw>>>(Wo, p_bw0, C_);
    {
        TBatch tb = {}; tb.A[0] = p_ba0; tb.B[0] = p_bw0; tb.Cc[0] = dout;
        hgemm<EPI_NONE><<<dim3(16, 16, 1), blk, HG_SMEM>>>(tb, C_, C_);
    }

    // 11) new_state (only if the harness expects both outputs)
    if (out_size >= T_ * C_ + (S_ + 1) * C_) {
        int n = H_ * S_ * S_;
        k_state<<<(n + EW - 1) / EW, EW>>>(dout, x, lenp);
    }
}

// round 9
// speedup vs baseline: 2.1867x; 1.1074x over previous
#include <cuda_runtime.h>
#include <cuda_bf16.h>
#include <math.h>
#include <stdint.h>

#define T_ 2048
#define C_ 2048
#define H_ 32
#define S_ 64
#define HKV_ 8
#define LMAA_ 32
#define LDEC_ 64
#define K3_ (3 * C_)   // 6144
#define SPLITK 4

// ---------------- f32 scratch ----------------
__device__ float g_sx [T_*C_];
__device__ float g_t1 [T_*5*LMAA_];
__device__ float g_t2 [T_*LDEC_];
__device__ float g_r  [T_*C_];
__device__ float g_k  [T_*HKV_*S_];
__device__ float g_v  [T_*HKV_*S_];
__device__ float g_ew [T_*C_];
__device__ float g_gate[T_*C_];
__device__ float g_sfin[H_*S_*S_];
__device__ float g_part[SPLITK * T_ * (5*LMAA_ + LDEC_)];

// ---------------- bf16 3-split buffers (A'=[hi|hi|lo], W'=[hi|lo|hi]) ----------------
__device__ __align__(128) __nv_bfloat16 g_ba_xxx[(size_t)T_ * K3_];
__device__ __align__(128) __nv_bfloat16 g_ba_r  [(size_t)T_ * K3_];   // xr, later reused for out
__device__ __align__(128) __nv_bfloat16 g_ba_k  [(size_t)T_ * K3_];
__device__ __align__(128) __nv_bfloat16 g_ba_v  [(size_t)T_ * K3_];
__device__ __align__(128) __nv_bfloat16 g_ba_w  [(size_t)T_ * K3_];
__device__ __align__(128) __nv_bfloat16 g_ba_g  [(size_t)T_ * K3_];
__device__ __align__(128) __nv_bfloat16 g_bwA[(size_t)2048 * K3_];    // Wq, later Wo
__device__ __align__(128) __nv_bfloat16 g_bwB[(size_t)2048 * K3_];    // Wg
__device__ __align__(128) __nv_bfloat16 g_bw1[(size_t)512 * K3_];     // Wk
__device__ __align__(128) __nv_bfloat16 g_bw2[(size_t)512 * K3_];     // Wv
__device__ __align__(128) __nv_bfloat16 g_bws1[(size_t)256 * K3_];    // maa_w1 (160->256)
__device__ __align__(128) __nv_bfloat16 g_bws2[(size_t)128 * K3_];    // dec_w1 (64->128)

// ---------------- epilogue ids ----------------
#define EPI_NONE  0
#define EPI_TANH  1
#define EPI_SIG   2
#define EPI_MIX   3
#define EPI_DECAY 4

// ---------------- mma.sync helpers ----------------
__device__ __forceinline__ uint32_t smem_u32(const void* p) {
    uint32_t a;
    asm("{ .reg .u64 t; cvta.to.shared.u64 t, %1; cvt.u32.u64 %0, t; }" : "=r"(a) : "l"(p));
    return a;
}
__device__ __forceinline__ void cp_async16(uint32_t saddr, const void* g) {
    asm volatile("cp.async.cg.shared.global [%0], [%1], 16;" :: "r"(saddr), "l"(g) : "memory");
}
__device__ __forceinline__ void ldmatrix_x4(uint32_t* r, uint32_t addr) {
    asm volatile("ldmatrix.sync.aligned.m8n8.x4.shared.b16 {%0,%1,%2,%3}, [%4];"
        : "=r"(r[0]), "=r"(r[1]), "=r"(r[2]), "=r"(r[3]) : "r"(addr));
}
__device__ __forceinline__ void mma16816(float* c, const uint32_t* a, uint32_t b0, uint32_t b1) {
    asm volatile("mma.sync.aligned.m16n8k16.row.col.f32.bf16.bf16.f32 "
        "{%0,%1,%2,%3}, {%4,%5,%6,%7}, {%8,%9}, {%0,%1,%2,%3};"
        : "+f"(c[0]), "+f"(c[1]), "+f"(c[2]), "+f"(c[3])
        : "r"(a[0]), "r"(a[1]), "r"(a[2]), "r"(a[3]), "r"(b0), "r"(b1));
}

struct TB {
    const __nv_bfloat16* A[4];
    const __nv_bfloat16* B[4];
    float*               Cc[4];
    int N[4];
    int ldc[4];
    int epi[4];
};

// ---------------- HMMA bf16 GEMM: C = A'[M,K'] @ B'[N,K']^T ----------------
// 128x128 CTA tile, 8 warps (2m x 4n), warp 64x32 m16n8k16, BK=64, 3-stage cp.async.
// splitStride>0: split-K mode (z = split idx, entry 0, kc0 = z*nch, C += z*splitStride).
__global__ __launch_bounds__(256, 2)
void hgemm(TB bt, int nch, int splitStride)
{
    const int z = blockIdx.z;
    const __nv_bfloat16* __restrict__ Ag;
    const __nv_bfloat16* __restrict__ Bg;
    float* __restrict__ Cg;
    int N, ldc, epi, kc0 = 0;
    if (splitStride > 0) {
        Ag = bt.A[0]; Bg = bt.B[0]; N = bt.N[0]; ldc = bt.ldc[0]; epi = bt.epi[0];
        Cg = bt.Cc[0] + (size_t)z * splitStride;
        kc0 = z * nch;
    } else {
        Ag = bt.A[z]; Bg = bt.B[z]; Cg = bt.Cc[z];
        N = bt.N[z]; ldc = bt.ldc[z]; epi = bt.epi[z];
    }
    if (blockIdx.x * 128 >= N) return;

    extern __shared__ char smem[];
    const uint32_t sbase = smem_u32(smem);   // 3 stages x (A 16KB | B 16KB)

    const int tid  = threadIdx.x;
    const int lane = tid & 31;
    const int wid  = tid >> 5;
    const int wm   = wid >> 2;    // 0..1
    const int wn   = wid & 3;     // 0..3
    const int bx = blockIdx.x, by = blockIdx.y;

    float acc[4][4][4];
    #pragma unroll
    for (int i = 0; i < 4; i++)
        #pragma unroll
        for (int j = 0; j < 4; j++)
            #pragma unroll
            for (int k = 0; k < 4; k++) acc[i][j][k] = 0.f;

    const __nv_bfloat16* Abase = Ag + (size_t)(by * 128) * K3_;
    const __nv_bfloat16* Bbase = Bg + (size_t)(bx * 128) * K3_;

    auto load_stage = [&](int kt, int s) {
        const uint32_t sa = sbase + s * 32768;
        const __nv_bfloat16* Agk = Abase + (size_t)(kc0 + kt) * 64;
        const __nv_bfloat16* Bgk = Bbase + (size_t)(kc0 + kt) * 64;
        #pragma unroll
        for (int q = 0; q < 4; q++) {
            const int c = q * 256 + tid;
            const int row = c >> 3, j = c & 7;
            uint32_t off = (uint32_t)(row * 128 + j * 16);
            off ^= (off >> 3) & 0x70;
            cp_async16(sa + off,         Agk + (size_t)row * K3_ + j * 8);
            cp_async16(sa + 16384 + off, Bgk + (size_t)row * K3_ + j * 8);
        }
        asm volatile("cp.async.commit_group;" ::: "memory");
    };

    const int a_roff = (wm * 64 + (lane & 15)) * 128 + (lane >> 4) * 16;
    const int b_roff = (wn * 32 + (lane & 7) + ((lane >> 4) << 3)) * 128 + ((lane >> 3) & 1) * 16;

    auto compute = [&](int s) {
        const uint32_t sa = sbase + s * 32768;
        const uint32_t sbb = sa + 16384;
        #pragma unroll
        for (int ks = 0; ks < 4; ks++) {
            uint32_t bf2[2][4];
            #pragma unroll
            for (int nt2 = 0; nt2 < 2; nt2++) {
                uint32_t off = (uint32_t)(b_roff + nt2 * 16 * 128 + ks * 32);
                off ^= (off >> 3) & 0x70;
                ldmatrix_x4(bf2[nt2], sbb + off);
            }
            uint32_t af[4][4];
            #pragma unroll
            for (int mt = 0; mt < 4; mt++) {
                uint32_t off = (uint32_t)(a_roff + mt * 16 * 128 + ks * 32);
                off ^= (off >> 3) & 0x70;
                ldmatrix_x4(af[mt], sa + off);
            }
            #pragma unroll
            for (int mt = 0; mt < 4; mt++)
                #pragma unroll
                for (int nt = 0; nt < 4; nt++)
                    mma16816(acc[mt][nt], af[mt],
                             bf2[nt >> 1][(nt & 1) * 2], bf2[nt >> 1][(nt & 1) * 2 + 1]);
        }
    };

    load_stage(0, 0);
    load_stage(1, 1);

    for (int kt = 0; kt < nch; kt++) {
        asm volatile("cp.async.wait_group 1;" ::: "memory");
        __syncthreads();
        if (kt + 2 < nch) load_stage(kt + 2, (kt + 2) % 3);
        else asm volatile("cp.async.commit_group;" ::: "memory");
        compute(kt % 3);
    }

    // epilogue (runtime epi: NONE / TANH / SIG)
    #pragma unroll
    for (int mt = 0; mt < 4; mt++) {
        #pragma unroll
        for (int hrow = 0; hrow < 2; hrow++) {
            const int row = by * 128 + wm * 64 + mt * 16 + hrow * 8 + (lane >> 2);
            float* crow = Cg + (size_t)row * ldc;
            #pragma unroll
            for (int nt = 0; nt < 4; nt++) {
                const int col = bx * 128 + wn * 32 + nt * 8 + (lane & 3) * 2;
                if (col >= N) continue;
                float v0 = acc[mt][nt][hrow * 2 + 0];
                float v1 = acc[mt][nt][hrow * 2 + 1];
                if (epi == EPI_TANH) { v0 = tanhf(v0); v1 = tanhf(v1); }
                else if (epi == EPI_SIG) { v0 = 1.f/(1.f+expf(-v0)); v1 = 1.f/(1.f+expf(-v1)); }
                *(float2*)&crow[col] = make_float2(v0, v1);
            }
        }
    }
}

// ---------------- split-K reducer + tanh ----------------
__global__ void k_red_tanh(const float* __restrict__ part, float* __restrict__ out,
                           int n, int stride)
{
    int i = blockIdx.x * blockDim.x + threadIdx.x;
    if (i >= n) return;
    float s = part[i] + part[(size_t)stride + i]
            + part[(size_t)2 * stride + i] + part[(size_t)3 * stride + i];
    out[i] = tanhf(s);
}

// weights: src[2048 x N] f32 -> dst[Npad x 6144] bf16 as rows n: [hi | lo | hi], transposed
__global__ void k_conv_w(const float* __restrict__ src, __nv_bfloat16* __restrict__ dst, int N)
{
    __shared__ float tile[32][33];
    const int n0 = blockIdx.x * 32;
    const int k0 = blockIdx.y * 32;
    const int tx = threadIdx.x, ty = threadIdx.y;  // (32, 8)
    #pragma unroll
    for (int yy = 0; yy < 32; yy += 8) {
        int n = n0 + tx, k = k0 + ty + yy;
        tile[ty + yy][tx] = (n < N) ? src[(size_t)k * N + n] : 0.f;
    }
    __syncthreads();
    #pragma unroll
    for (int yy = 0; yy < 32; yy += 8) {
        int n = n0 + ty + yy;
        int k = k0 + tx;
        float a = tile[tx][ty + yy];
        __nv_bfloat16 hi = __float2bfloat16(a);
        __nv_bfloat16 lo = __float2bfloat16(a - __bfloat162float(hi));
        size_t base = (size_t)n * K3_;
        dst[base + k] = hi;
        dst[base + C_ + k] = lo;
        dst[base + 2 * C_ + k] = hi;
    }
}

// ---------------- FFMA2 GEMM (small-K: MIX K=32 -> bf16 split out, DECAY K=64 -> f32) ----
struct Batch {
    const float* A[8];
    const float* B[8];
    void*        Cc[8];
    const float* vec[8];
};

template<int EPI>
__global__ __launch_bounds__(256, 2)
void gemm128(Batch bt, int lda, int ldb, int ldc, int N, int K,
             const float* __restrict__ aux1, const float* __restrict__ aux2)
{
    __shared__ float2 As[2][16][128];
    __shared__ float  Bs[2][16][128];

    const int z = blockIdx.z;
    const float* __restrict__ A   = bt.A[z];
    const float* __restrict__ B   = bt.B[z];
    const float* __restrict__ vec = bt.vec[z];

    const int tid = threadIdx.x;
    const int bx = blockIdx.x, by = blockIdx.y;
    const int arow = tid >> 1,  acol = (tid & 1) * 8;
    const int brow = tid >> 4,  bcol = (tid & 15) * 8;
    const int tx = tid & 15,    ty = tid >> 4;

    unsigned long long acc[8][4];
    #pragma unroll
    for (int i = 0; i < 8; i++)
        #pragma unroll
        for (int j = 0; j < 4; j++) acc[i][j] = 0ULL;

    const float* Ap = A + (size_t)(by * 128 + arow) * lda + acol;
    const int gcolb = bx * 128 + bcol;

    float4 a0, a1, b0, b1;
    auto loadAB = [&](int k0) {
        a0 = *(const float4*)(Ap + k0);
        a1 = *(const float4*)(Ap + k0 + 4);
        const float* bp = B + (size_t)(k0 + brow) * ldb + gcolb;
        b0 = *(const float4*)bp;
        b1 = *(const float4*)(bp + 4);
    };
    auto storeAB = [&](int buf) {
        As[buf][acol + 0][arow] = make_float2(a0.x, a0.x);
        As[buf][acol + 1][arow] = make_float2(a0.y, a0.y);
        As[buf][acol + 2][arow] = make_float2(a0.z, a0.z);
        As[buf][acol + 3][arow] = make_float2(a0.w, a0.w);
        As[buf][acol + 4][arow] = make_float2(a1.x, a1.x);
        As[buf][acol + 5][arow] = make_float2(a1.y, a1.y);
        As[buf][acol + 6][arow] = make_float2(a1.z, a1.z);
        As[buf][acol + 7][arow] = make_float2(a1.w, a1.w);
        *(float4*)&Bs[buf][brow][bcol]     = b0;
        *(float4*)&Bs[buf][brow][bcol + 4] = b1;
    };

    loadAB(0);
    storeAB(0);
    __syncthreads();

    const int nt = K >> 4;
    for (int kt = 0; kt < nt; kt++) {
        const int cur = kt & 1;
        if (kt + 1 < nt) loadAB((kt + 1) << 4);

        #pragma unroll
        for (int kk = 0; kk < 16; kk++) {
            unsigned long long a2[8], b2[4];
            const ulonglong2* ap = (const ulonglong2*)&As[cur][kk][ty * 8];
            ulonglong2 w;
            w = ap[0]; a2[0] = w.x; a2[1] = w.y;
            w = ap[1]; a2[2] = w.x; a2[3] = w.y;
            w = ap[2]; a2[4] = w.x; a2[5] = w.y;
            w = ap[3]; a2[6] = w.x; a2[7] = w.y;
            const ulonglong2* bp2 = (const ulonglong2*)&Bs[cur][kk][tx * 8];
            w = bp2[0]; b2[0] = w.x; b2[1] = w.y;
            w = bp2[1]; b2[2] = w.x; b2[3] = w.y;
            #pragma unroll
            for (int i = 0; i < 8; i++)
                #pragma unroll
                for (int j = 0; j < 4; j++)
                    asm("fma.rn.f32x2 %0, %1, %2, %0;"
                        : "+l"(acc[i][j]) : "l"(a2[i]), "l"(b2[j]));
        }

        if (kt + 1 < nt) storeAB(cur ^ 1);
        __syncthreads();
    }

    #pragma unroll
    for (int i = 0; i < 8; i++) {
        const int row = by * 128 + ty * 8 + i;
        #pragma unroll
        for (int j = 0; j < 4; j++) {
            const int col = bx * 128 + tx * 8 + 2 * j;
            float v0 = __uint_as_float((unsigned)(acc[i][j] & 0xffffffffULL));
            float v1 = __uint_as_float((unsigned)(acc[i][j] >> 32));
            if (EPI == EPI_MIX) {
                // out = x + sx*(vec + acc), written as bf16 [hi|hi|lo] split
                size_t idx = (size_t)row * C_ + col;
                v0 = aux1[idx]     + aux2[idx]     * (vec[col]     + v0);
                v1 = aux1[idx + 1] + aux2[idx + 1] * (vec[col + 1] + v1);
                __nv_bfloat16 h0 = __float2bfloat16(v0);
                __nv_bfloat16 h1 = __float2bfloat16(v1);
                __nv_bfloat16 l0 = __float2bfloat16(v0 - __bfloat162float(h0));
                __nv_bfloat16 l1 = __float2bfloat16(v1 - __bfloat162float(h1));
                __nv_bfloat162 hh; hh.x = h0; hh.y = h1;
                __nv_bfloat162 ll; ll.x = l0; ll.y = l1;
                __nv_bfloat16* bout = (__nv_bfloat16*)bt.Cc[z];
                size_t base = (size_t)row * K3_;
                *(__nv_bfloat162*)&bout[base + col]          = hh;
                *(__nv_bfloat162*)&bout[base + C_ + col]     = hh;
                *(__nv_bfloat162*)&bout[base + 2 * C_ + col] = ll;
            } else {  // EPI_DECAY
                float* crow = (float*)bt.Cc[z] + (size_t)row * ldc;
                float lw0 = fmaxf(-expf(v0 + vec[col]), -5.0f);
                float lw1 = fmaxf(-expf(v1 + vec[col + 1]), -5.0f);
                *(float2*)&crow[col] = make_float2(expf(lw0), expf(lw1));
            }
        }
    }
}

// ---------------- token shift: writes sx (f32) + xxx (bf16 split) ----------------
__global__ void k_shift(const float* __restrict__ x, const float* __restrict__ state,
                        const unsigned char* __restrict__ ns,
                        const float* __restrict__ maa_x)
{
    int idx = blockIdx.x * blockDim.x + threadIdx.x;
    if (idx >= T_ * C_) return;
    int t = idx >> 11;
    int c = idx & 2047;
    float prev = (t == 0) ? state[c] : x[idx - C_];
    if (ns[t]) prev = 0.f;
    float s = prev - x[idx];
    g_sx[idx] = s;
    float v = x[idx] + s * maa_x[c];
    __nv_bfloat16 hi = __float2bfloat16(v);
    __nv_bfloat16 lo = __float2bfloat16(v - __bfloat162float(hi));
    size_t base = (size_t)t * K3_;
    g_ba_xxx[base + c]          = hi;
    g_ba_xxx[base + C_ + c]     = hi;
    g_ba_xxx[base + 2 * C_ + c] = lo;
}

// ---------------- the RWKV scan v2: batched output reduction ----------------
// 512 threads: vcol = tid>>3, kg = tid&7. Per step: smem-staged inputs (double buf),
// packed f32x2 state update, partial dumped to 16-deep pbuf ring; every 8 steps a
// batched reduction produces gated outputs written as bf16 [hi|hi|lo] split.
__global__ __launch_bounds__(512)
void k_scan(const float* __restrict__ state, const unsigned char* __restrict__ ns,
            __nv_bfloat16* __restrict__ out_split)
{
    const int h = blockIdx.x;
    const int tid = threadIdx.x;
    const int vcol = tid >> 3;
    const int kg = tid & 7;

    unsigned long long s2[4];
    #pragma unroll
    for (int j2 = 0; j2 < 4; j2++) {
        float slo = state[C_ + h * 4096 + (kg * 8 + 2 * j2) * 64 + vcol];
        float shi = state[C_ + h * 4096 + (kg * 8 + 2 * j2 + 1) * 64 + vcol];
        asm("mov.b64 %0, {%1, %2};" : "=l"(s2[j2]) : "f"(slo), "f"(shi));
    }

    __shared__ float sh[2][4 * 64];        // [r | keff | ew | v], double buffered
    __shared__ float gbuf[16][64];         // gate ring
    __shared__ float pbuf[16][512];        // partial ring
    __shared__ unsigned char nsh[T_];
    for (int i = tid; i < T_; i += 512) nsh[i] = ns[i];

    const int a  = tid >> 6;
    const int li = tid & 63;
    const bool loader = (a < 5);
    const size_t baseC  = (size_t)h * 64 + li;
    const size_t baseKV = (size_t)(h >> 2) * 64 + li;

    auto gload = [&](int t) -> float {
        switch (a) {
            case 0:  return g_r[(size_t)t * C_ + baseC];
            case 1: {
                float kv = g_k [(size_t)t * 512 + baseKV];
                float ew = g_ew[(size_t)t * C_ + baseC];
                return kv * (1.f - ew);
            }
            case 2:  return g_ew[(size_t)t * C_ + baseC];
            case 3:  return g_v [(size_t)t * 512 + baseKV];
            default: return g_gate[(size_t)t * C_ + baseC];
        }
    };

    float rr[8];
    if (loader) {
        #pragma unroll
        for (int p = 0; p < 8; p++) rr[p] = gload(p);
        if (a < 4) sh[0][a * 64 + li] = rr[0];
        else       gbuf[0][li] = rr[0];
    }
    __syncthreads();

    #pragma unroll 8
    for (int t = 0; t < T_; t++) {
        if (loader) {
            if (t + 8 < T_) rr[(t + 8) & 7] = gload(t + 8);
            if (t + 1 < T_) {
                float val = rr[(t + 1) & 7];
                if (a < 4) sh[(t + 1) & 1][a * 64 + li] = val;
                else       gbuf[(t + 1) & 15][li] = val;
            }
        }
        const float* S = sh[t & 1];

        float vv = S[3 * 64 + vcol];
        unsigned long long vv2;
        asm("mov.b64 %0, {%1, %1};" : "=l"(vv2) : "f"(vv));

        const bool reset = (nsh[t] != 0);

        const ulonglong2* rp = (const ulonglong2*)&S[0 * 64 + kg * 8];
        const ulonglong2* kp = (const ulonglong2*)&S[1 * 64 + kg * 8];
        const ulonglong2* wp = (const ulonglong2*)&S[2 * 64 + kg * 8];
        ulonglong2 rA = rp[0], rB = rp[1];
        ulonglong2 kA = kp[0], kB = kp[1];
        ulonglong2 wA = wp[0], wB = wp[1];
        unsigned long long r2[4] = { rA.x, rA.y, rB.x, rB.y };
        unsigned long long k2[4] = { kA.x, kA.y, kB.x, kB.y };
        unsigned long long w2[4] = { wA.x, wA.y, wB.x, wB.y };

        unsigned long long ps2 = 0ULL;
        #pragma unroll
        for (int j2 = 0; j2 < 4; j2++) {
            if (reset) s2[j2] = 0ULL;
            unsigned long long kv2;
            asm("mul.rn.f32x2 %0, %1, %2;"     : "=l"(kv2)    : "l"(k2[j2]), "l"(vv2));
            asm("fma.rn.f32x2 %0, %1, %2, %3;" : "=l"(s2[j2]) : "l"(s2[j2]), "l"(w2[j2]), "l"(kv2));
            asm("fma.rn.f32x2 %0, %1, %2, %0;" : "+l"(ps2)    : "l"(r2[j2]), "l"(s2[j2]));
        }

        float plo = __uint_as_float((unsigned)(ps2 & 0xffffffffULL));
        float phi = __uint_as_float((unsigned)(ps2 >> 32));
        pbuf[t & 15][tid] = plo + phi;
        __syncthreads();

        if ((t & 7) == 7) {
            // batched reduction for steps [t-7, t]: thread -> (st, vc)
            const int st = tid >> 6;       // 0..7
            const int vc = tid & 63;
            const int slot = (t - 7 + st) & 15;
            const float4* p4 = (const float4*)&pbuf[slot][vc * 8];
            float4 x0 = p4[0], x1 = p4[1];
            float o = ((x0.x + x0.y) + (x0.z + x0.w)) + ((x1.x + x1.y) + (x1.z + x1.w));
            o *= gbuf[slot][vc];
            const int trow = t - 7 + st;
            __nv_bfloat16 hi = __float2bfloat16(o);
            __nv_bfloat16 lo = __float2bfloat16(o - __bfloat162float(hi));
            size_t base = (size_t)trow * K3_;
            int c = h * 64 + vc;
            out_split[base + c]          = hi;
            out_split[base + C_ + c]     = hi;
            out_split[base + 2 * C_ + c] = lo;
        }
    }

    #pragma unroll
    for (int j2 = 0; j2 < 4; j2++) {
        float slo = __uint_as_float((unsigned)(s2[j2] & 0xffffffffULL));
        float shi = __uint_as_float((unsigned)(s2[j2] >> 32));
        g_sfin[h * 4096 + (kg * 8 + 2 * j2) * 64 + vcol]     = slo;
        g_sfin[h * 4096 + (kg * 8 + 2 * j2 + 1) * 64 + vcol] = shi;
    }
}

// ---------------- new_state writer ----------------
__global__ void k_state(float* __restrict__ dout, const float* __restrict__ x,
                        const int* __restrict__ lenp)
{
    int idx = blockIdx.x * blockDim.x + threadIdx.x;
    int L = lenp ? lenp[0] : T_;
    if (idx < C_)
        dout[(size_t)T_ * C_ + idx] = x[(size_t)(L - 1) * C_ + idx];
    if (idx < H_ * S_ * S_)
        dout[(size_t)T_ * C_ + C_ + idx] = g_sfin[idx];
}

// ---------------- host-side orchestration ----------------
template <typename Sym>
static void* devaddr_v(Sym& sym) {
    void* p = nullptr;
    cudaGetSymbolAddress(&p, sym);
    return p;
}

#define HG_SMEM (3 * 32768)

extern "C" void kernel_launch(void* const* d_in, const int* in_sizes, int n_in,
                              void* d_out, int out_size)
{
    int i = 0;
    const float* x       = (const float*)d_in[i++];
    const float* state   = (const float*)d_in[i++];
    const unsigned char* ns = (const unsigned char*)d_in[i++];
    const int* lenp = nullptr;
    if (n_in >= 20) { lenp = (const int*)d_in[i++]; }
    const float* maa_x = (const float*)d_in[i++];
    const float* maa_r = (const float*)d_in[i++];
    const float* maa_k = (const float*)d_in[i++];
    const float* maa_v = (const float*)d_in[i++];
    const float* maa_w = (const float*)d_in[i++];
    const float* maa_g = (const float*)d_in[i++];
    const float* maa_w1 = (const float*)d_in[i++];  // [C, 160]
    const float* maa_w2 = (const float*)d_in[i++];  // [5, 32, C]
    const float* tdecay = (const float*)d_in[i++];  // [C]
    const float* dec_w1 = (const float*)d_in[i++];  // [C, 64]
    const float* dec_w2 = (const float*)d_in[i++];  // [64, C]
    const float* Wq = (const float*)d_in[i++];      // [C, C]
    const float* Wk = (const float*)d_in[i++];      // [C, 512]
    const float* Wv = (const float*)d_in[i++];      // [C, 512]
    const float* Wg = (const float*)d_in[i++];      // [C, C]
    const float* Wo = (const float*)d_in[i++];      // [C, C]
    float* dout = (float*)d_out;

    float* p_sx   = (float*)devaddr_v(g_sx);
    float* p_t1   = (float*)devaddr_v(g_t1);
    float* p_t2   = (float*)devaddr_v(g_t2);
    float* p_r    = (float*)devaddr_v(g_r);
    float* p_k    = (float*)devaddr_v(g_k);
    float* p_v    = (float*)devaddr_v(g_v);
    float* p_ew   = (float*)devaddr_v(g_ew);
    float* p_gate = (float*)devaddr_v(g_gate);
    float* p_part = (float*)devaddr_v(g_part);
    __nv_bfloat16* p_ba_xxx = (__nv_bfloat16*)devaddr_v(g_ba_xxx);
    __nv_bfloat16* p_ba_r   = (__nv_bfloat16*)devaddr_v(g_ba_r);
    __nv_bfloat16* p_ba_k   = (__nv_bfloat16*)devaddr_v(g_ba_k);
    __nv_bfloat16* p_ba_v   = (__nv_bfloat16*)devaddr_v(g_ba_v);
    __nv_bfloat16* p_ba_w   = (__nv_bfloat16*)devaddr_v(g_ba_w);
    __nv_bfloat16* p_ba_g   = (__nv_bfloat16*)devaddr_v(g_ba_g);
    __nv_bfloat16* p_bwA  = (__nv_bfloat16*)devaddr_v(g_bwA);
    __nv_bfloat16* p_bwB  = (__nv_bfloat16*)devaddr_v(g_bwB);
    __nv_bfloat16* p_bw1  = (__nv_bfloat16*)devaddr_v(g_bw1);
    __nv_bfloat16* p_bw2  = (__nv_bfloat16*)devaddr_v(g_bw2);
    __nv_bfloat16* p_bws1 = (__nv_bfloat16*)devaddr_v(g_bws1);
    __nv_bfloat16* p_bws2 = (__nv_bfloat16*)devaddr_v(g_bws2);

    cudaFuncSetAttribute(hgemm, cudaFuncAttributeMaxDynamicSharedMemorySize, HG_SMEM);

    const int EW = 256;
    const int GE = (T_ * C_ + EW - 1) / EW;
    dim3 blk(256);
    dim3 cw(32, 8);

    // 0) weight conversions (independent of everything)
    k_conv_w<<<dim3(C_ / 32, 64), cw>>>(Wq, p_bwA, C_);
    k_conv_w<<<dim3(C_ / 32, 64), cw>>>(Wg, p_bwB, C_);
    k_conv_w<<<dim3(512 / 32, 64), cw>>>(Wk, p_bw1, HKV_ * S_);
    k_conv_w<<<dim3(512 / 32, 64), cw>>>(Wv, p_bw2, HKV_ * S_);
    k_conv_w<<<dim3(256 / 32, 64), cw>>>(maa_w1, p_bws1, 5 * LMAA_);
    k_conv_w<<<dim3(128 / 32, 64), cw>>>(dec_w1, p_bws2, LDEC_);

    // 1) token shift -> sx (f32) + ba_xxx (bf16 split)
    k_shift<<<GE, EW>>>(x, state, ns, maa_x);

    // 2) t1 = tanh(xxx @ maa_w1) [T,160]: split-K 4 + reduce
    {
        TB tb = {};
        tb.A[0] = p_ba_xxx; tb.B[0] = p_bws1; tb.Cc[0] = p_part;
        tb.N[0] = 5 * LMAA_; tb.ldc[0] = 5 * LMAA_; tb.epi[0] = EPI_NONE;
        hgemm<<<dim3(2, 16, SPLITK), blk, HG_SMEM>>>(tb, 96 / SPLITK, T_ * 5 * LMAA_);
        int n = T_ * 5 * LMAA_;
        k_red_tanh<<<(n + EW - 1) / EW, EW>>>(p_part, p_t1, n, n);
    }

    // 3) MIX (FFMA2, K=32): writes 5 bf16-split activation buffers
    {
        Batch bt = {};
        const float* vecs[5] = { maa_r, maa_k, maa_v, maa_w, maa_g };
        void* outs[5] = { p_ba_r, p_ba_k, p_ba_v, p_ba_w, p_ba_g };
        for (int z = 0; z < 5; z++) {
            bt.A[z]  = p_t1 + z * LMAA_;
            bt.B[z]  = maa_w2 + (size_t)z * LMAA_ * C_;
            bt.Cc[z] = outs[z];
            bt.vec[z] = vecs[z];
        }
        gemm128<EPI_MIX><<<dim3(C_ / 128, T_ / 128, 5), blk>>>(bt, 5 * LMAA_, C_, C_, C_, LMAA_, x, p_sx);
    }

    // 4) r + gate + k + v in ONE launch (z=4)
    {
        TB tb = {};
        tb.A[0] = p_ba_r; tb.B[0] = p_bwA; tb.Cc[0] = p_r;    tb.N[0] = C_;  tb.ldc[0] = C_;  tb.epi[0] = EPI_NONE;
        tb.A[1] = p_ba_g; tb.B[1] = p_bwB; tb.Cc[1] = p_gate; tb.N[1] = C_;  tb.ldc[1] = C_;  tb.epi[1] = EPI_SIG;
        tb.A[2] = p_ba_k; tb.B[2] = p_bw1; tb.Cc[2] = p_k;    tb.N[2] = 512; tb.ldc[2] = 512; tb.epi[2] = EPI_NONE;
        tb.A[3] = p_ba_v; tb.B[3] = p_bw2; tb.Cc[3] = p_v;    tb.N[3] = 512; tb.ldc[3] = 512; tb.epi[3] = EPI_NONE;
        hgemm<<<dim3(16, 16, 4), blk, HG_SMEM>>>(tb, 96, 0);
    }

    // 5) t2 = tanh(xw @ dec_w1) [T,64]: split-K 4 + reduce
    {
        TB tb = {};
        float* part2 = p_part;  // reuse (t1 partials consumed)
        tb.A[0] = p_ba_w; tb.B[0] = p_bws2; tb.Cc[0] = part2;
        tb.N[0] = LDEC_; tb.ldc[0] = LDEC_; tb.epi[0] = EPI_NONE;
        hgemm<<<dim3(1, 16, SPLITK), blk, HG_SMEM>>>(tb, 96 / SPLITK, T_ * LDEC_);
        int n = T_ * LDEC_;
        k_red_tanh<<<(n + EW - 1) / EW, EW>>>(part2, p_t2, n, n);
    }

    // 6) ew = exp(max(-exp(t2@dec_w2 + tdecay), -5)) (FFMA2, K=64)
    {
        Batch bt = {};
        bt.A[0] = p_t2; bt.B[0] = dec_w2; bt.Cc[0] = p_ew; bt.vec[0] = tdecay;
        gemm128<EPI_DECAY><<<dim3(C_ / 128, T_ / 128, 1), blk>>>(bt, LDEC_, C_, C_, C_, LDEC_, nullptr, nullptr);
    }

    // 7) Wo conversion (bwA free after step 4)
    k_conv_w<<<dim3(C_ / 32, 64), cw>>>(Wo, p_bwA, C_);

    // 8) scan: writes gated output as bf16 split into ba_r (reused)
    k_scan<<<H_, 512>>>(state, ns, p_ba_r);

    // 9) final projection: dout = (out*gate) @ Wo
    {
        TB tb = {};
        tb.A[0] = p_ba_r; tb.B[0] = p_bwA; tb.Cc[0] = dout;
        tb.N[0] = C_; tb.ldc[0] = C_; tb.epi[0] = EPI_NONE;
        hgemm<<<dim3(16, 16, 1), blk, HG_SMEM>>>(tb, 96, 0);
    }

    // 10) new_state (only if the harness expects both outputs)
    if (out_size >= T_ * C_ + (S_ + 1) * C_) {
        int n = H_ * S_ * S_;
        k_state<<<(n + EW - 1) / EW, EW>>>(dout, x, lenp);
    }
}